// round 1
// baseline (speedup 1.0000x reference)
#include <cuda_runtime.h>
#include <math.h>

#define B_ 8
#define S_ 2048
#define D_ 768
#define H_ 12
#define HD_ 64

// Scratch (allocation-free rule: __device__ globals)
__device__ __align__(16) float g_Q[B_*H_*S_*HD_];
__device__ __align__(16) float g_K[B_*H_*S_*HD_];
__device__ __align__(16) float g_V[B_*H_*S_*HD_];
__device__ __align__(16) float g_ctx[B_*S_*D_];

// ---------------------------------------------------------------------------
// Generic tiled GEMM body: C[128 x 64] tile = A[M,K] * B[K,N] + bias
// A row-major (lda), B row-major (ldb), C row-major (ldc).
// 256 threads, thread computes 8x4. BK=16.
// ---------------------------------------------------------------------------
__device__ __forceinline__ void gemm_tile(
    const float* __restrict__ A, int lda,
    const float* __restrict__ Bm, int ldb,
    const float* __restrict__ bias,
    float* __restrict__ C, int ldc,
    int K, int m0, int n0)
{
    __shared__ float As[16][132];   // transposed A tile, padded (conflict-free)
    __shared__ float Bs[16][64];

    const int t  = threadIdx.x;
    const int tx = t & 15;          // 16 col-groups of 4
    const int ty = t >> 4;          // 16 row-groups of 8

    float acc[8][4];
#pragma unroll
    for (int i = 0; i < 8; i++)
#pragma unroll
        for (int j = 0; j < 4; j++) acc[i][j] = 0.0f;

    for (int k0 = 0; k0 < K; k0 += 16) {
        // Load A tile 128x16, store transposed As[k][m]
#pragma unroll
        for (int j = 0; j < 2; j++) {
            int fid = t * 2 + j;          // 0..511 float4s
            int row = fid >> 2;           // 0..127
            int kq  = fid & 3;            // k-quad
            float4 v = *reinterpret_cast<const float4*>(
                &A[(size_t)(m0 + row) * lda + k0 + kq * 4]);
            As[kq * 4 + 0][row] = v.x;
            As[kq * 4 + 1][row] = v.y;
            As[kq * 4 + 2][row] = v.z;
            As[kq * 4 + 3][row] = v.w;
        }
        // Load B tile 16x64
        {
            int kr = t >> 4, nq = t & 15;
            *reinterpret_cast<float4*>(&Bs[kr][nq * 4]) =
                *reinterpret_cast<const float4*>(
                    &Bm[(size_t)(k0 + kr) * ldb + n0 + nq * 4]);
        }
        __syncthreads();

#pragma unroll
        for (int kk = 0; kk < 16; kk++) {
            float4 a0 = *reinterpret_cast<float4*>(&As[kk][ty * 8]);
            float4 a1 = *reinterpret_cast<float4*>(&As[kk][ty * 8 + 4]);
            float4 bv = *reinterpret_cast<float4*>(&Bs[kk][tx * 4]);
            float a[8] = {a0.x, a0.y, a0.z, a0.w, a1.x, a1.y, a1.z, a1.w};
            float b[4] = {bv.x, bv.y, bv.z, bv.w};
#pragma unroll
            for (int i = 0; i < 8; i++)
#pragma unroll
                for (int j = 0; j < 4; j++)
                    acc[i][j] += a[i] * b[j];
        }
        __syncthreads();
    }

    float4 bb = *reinterpret_cast<const float4*>(&bias[n0 + tx * 4]);
#pragma unroll
    for (int i = 0; i < 8; i++) {
        int m = m0 + ty * 8 + i;
        float4 o;
        o.x = acc[i][0] + bb.x;
        o.y = acc[i][1] + bb.y;
        o.z = acc[i][2] + bb.z;
        o.w = acc[i][3] + bb.w;
        *reinterpret_cast<float4*>(&C[(size_t)m * ldc + n0 + tx * 4]) = o;
    }
}

// ---------------------------------------------------------------------------
// QKV projection: grid (S/128, B*H, 3)
// ---------------------------------------------------------------------------
__global__ void __launch_bounds__(256)
qkv_kernel(const float* __restrict__ x,
           const float* __restrict__ Wq, const float* __restrict__ bq,
           const float* __restrict__ Wk, const float* __restrict__ bk,
           const float* __restrict__ Wv, const float* __restrict__ bv)
{
    int bh = blockIdx.y;
    int b  = bh / H_;
    int h  = bh % H_;
    int m0 = blockIdx.x * 128;
    int z  = blockIdx.z;

    const float* W    = (z == 0) ? Wq : (z == 1) ? Wk : Wv;
    const float* bias = (z == 0) ? bq : (z == 1) ? bk : bv;
    float*       Out  = (z == 0) ? g_Q : (z == 1) ? g_K : g_V;

    gemm_tile(x + (size_t)b * S_ * D_, D_,
              W + (size_t)h * D_ * HD_, HD_,
              bias + h * HD_,
              Out + (size_t)bh * S_ * HD_, HD_,
              D_, m0, 0);
}

// ---------------------------------------------------------------------------
// Output projection: ctx[16384,768] @ Wp[768,768] + bp. grid (128, 12)
// ---------------------------------------------------------------------------
__global__ void __launch_bounds__(256)
proj_kernel(const float* __restrict__ Wp, const float* __restrict__ bp,
            float* __restrict__ out)
{
    gemm_tile(g_ctx, D_, Wp, D_, bp, out, D_, D_,
              blockIdx.x * 128, blockIdx.y * 64);
}

// ---------------------------------------------------------------------------
// Flash attention: grid (S/128, B*H), 256 threads.
// Each CTA: 128 query rows for one (b,h); iterate 64-key tiles.
// Thread t: cg = t&3 -> e/c range [cg*16, cg*16+16); rows r1=t>>2 and r1+64.
// Dynamic smem: QT[64][128] + KT[64][64] + Vs[64][64] + Ps[128][68]
// ---------------------------------------------------------------------------
#define ATTN_SMEM ((64*128 + 64*64 + 64*64 + 128*68) * 4)

__global__ void __launch_bounds__(256)
attn_kernel()
{
    extern __shared__ float sm[];
    float* QT = sm;                    // QT[e*128 + r]  (e-major, conflict-free reads)
    float* KT = QT + 64 * 128;         // KT[e*64 + c]
    float* Vs = KT + 64 * 64;          // Vs[c*64 + e]
    float* Ps = Vs + 64 * 64;          // Ps[r*68 + c]   (pad 68 -> conflict-free reads)

    const int bh = blockIdx.y;
    const int b  = bh / H_;
    const int h  = bh % H_;
    const int m0 = blockIdx.x * 128;

    const float* Qg = g_Q + (size_t)bh * S_ * HD_;
    const float* Kg = g_K + (size_t)bh * S_ * HD_;
    const float* Vg = g_V + (size_t)bh * S_ * HD_;

    const int t  = threadIdx.x;
    const int cg = t & 3;
    const int r1 = t >> 2;             // 0..63
    const int e0 = cg * 16;            // this thread's e/c column range

    const float rscale = 1.0f / (8.0f + 1e-6f);   // 1/(sqrt(64)+eps)

    // Load Q (pre-scaled), transposed into QT
#pragma unroll
    for (int rr = 0; rr < 2; rr++) {
        int r = r1 + rr * 64;
#pragma unroll
        for (int q4 = 0; q4 < 4; q4++) {
            float4 v = *reinterpret_cast<const float4*>(
                &Qg[(size_t)(m0 + r) * HD_ + e0 + q4 * 4]);
            QT[(e0 + q4 * 4 + 0) * 128 + r] = v.x * rscale;
            QT[(e0 + q4 * 4 + 1) * 128 + r] = v.y * rscale;
            QT[(e0 + q4 * 4 + 2) * 128 + r] = v.z * rscale;
            QT[(e0 + q4 * 4 + 3) * 128 + r] = v.w * rscale;
        }
    }

    float m1 = -1e30f, l1 = 0.0f;
    float m2 = -1e30f, l2 = 0.0f;
    float a1[16], a2[16];
#pragma unroll
    for (int j = 0; j < 16; j++) { a1[j] = 0.0f; a2[j] = 0.0f; }

    // K load mapping: row ck = t&63, e-range (t>>6)*16
    const int ck  = t & 63;
    const int ke0 = (t >> 6) * 16;

    for (int n0 = 0; n0 < S_; n0 += 64) {
        // Prefetch K/V tile into registers (overlaps prior compute)
        float4 kv[4], vv[4];
#pragma unroll
        for (int j = 0; j < 4; j++)
            kv[j] = *reinterpret_cast<const float4*>(
                &Kg[(size_t)(n0 + ck) * HD_ + ke0 + j * 4]);
#pragma unroll
        for (int j = 0; j < 4; j++)
            vv[j] = *reinterpret_cast<const float4*>(
                &Vg[(size_t)(n0 + r1) * HD_ + e0 + j * 4]);

        __syncthreads();   // prior tile's smem reads complete
#pragma unroll
        for (int j = 0; j < 4; j++) {
            KT[(ke0 + j * 4 + 0) * 64 + ck] = kv[j].x;
            KT[(ke0 + j * 4 + 1) * 64 + ck] = kv[j].y;
            KT[(ke0 + j * 4 + 2) * 64 + ck] = kv[j].z;
            KT[(ke0 + j * 4 + 3) * 64 + ck] = kv[j].w;
        }
#pragma unroll
        for (int j = 0; j < 4; j++)
            *reinterpret_cast<float4*>(&Vs[r1 * 64 + e0 + j * 4]) = vv[j];
        __syncthreads();

        // ---- scores: s[r][c] = sum_e Q[r][e]*K[c][e] (Q pre-scaled) ----
        float s1[16], s2[16];
#pragma unroll
        for (int j = 0; j < 16; j++) { s1[j] = 0.0f; s2[j] = 0.0f; }

#pragma unroll 4
        for (int e = 0; e < 64; e++) {
            float q1 = QT[e * 128 + r1];
            float q2 = QT[e * 128 + r1 + 64];
#pragma unroll
            for (int j4 = 0; j4 < 4; j4++) {
                float4 k4 = *reinterpret_cast<float4*>(&KT[e * 64 + e0 + j4 * 4]);
                s1[j4 * 4 + 0] += q1 * k4.x;  s2[j4 * 4 + 0] += q2 * k4.x;
                s1[j4 * 4 + 1] += q1 * k4.y;  s2[j4 * 4 + 1] += q2 * k4.y;
                s1[j4 * 4 + 2] += q1 * k4.z;  s2[j4 * 4 + 2] += q2 * k4.z;
                s1[j4 * 4 + 3] += q1 * k4.w;  s2[j4 * 4 + 3] += q2 * k4.w;
            }
        }

        // ---- online softmax (per row, 4 lanes cooperate via shfl) ----
        float tm1 = s1[0], tm2 = s2[0];
#pragma unroll
        for (int j = 1; j < 16; j++) { tm1 = fmaxf(tm1, s1[j]); tm2 = fmaxf(tm2, s2[j]); }
        tm1 = fmaxf(tm1, __shfl_xor_sync(0xffffffffu, tm1, 1));
        tm1 = fmaxf(tm1, __shfl_xor_sync(0xffffffffu, tm1, 2));
        tm2 = fmaxf(tm2, __shfl_xor_sync(0xffffffffu, tm2, 1));
        tm2 = fmaxf(tm2, __shfl_xor_sync(0xffffffffu, tm2, 2));

        float mn1 = fmaxf(m1, tm1);
        float mn2 = fmaxf(m2, tm2);
        float corr1 = __expf(m1 - mn1);
        float corr2 = __expf(m2 - mn2);

        float sum1 = 0.0f, sum2 = 0.0f;
#pragma unroll
        for (int j = 0; j < 16; j++) {
            float p1 = __expf(s1[j] - mn1);
            float p2 = __expf(s2[j] - mn2);
            s1[j] = p1; s2[j] = p2;
            sum1 += p1; sum2 += p2;
        }
        sum1 += __shfl_xor_sync(0xffffffffu, sum1, 1);
        sum1 += __shfl_xor_sync(0xffffffffu, sum1, 2);
        sum2 += __shfl_xor_sync(0xffffffffu, sum2, 1);
        sum2 += __shfl_xor_sync(0xffffffffu, sum2, 2);

        l1 = l1 * corr1 + sum1;  m1 = mn1;
        l2 = l2 * corr2 + sum2;  m2 = mn2;
#pragma unroll
        for (int j = 0; j < 16; j++) { a1[j] *= corr1; a2[j] *= corr2; }

        // Stage P in smem (contiguous 16 cols -> 4 STS.128 per row)
#pragma unroll
        for (int j4 = 0; j4 < 4; j4++) {
            float4 p4;
            p4.x = s1[j4 * 4 + 0]; p4.y = s1[j4 * 4 + 1];
            p4.z = s1[j4 * 4 + 2]; p4.w = s1[j4 * 4 + 3];
            *reinterpret_cast<float4*>(&Ps[r1 * 68 + e0 + j4 * 4]) = p4;
            p4.x = s2[j4 * 4 + 0]; p4.y = s2[j4 * 4 + 1];
            p4.z = s2[j4 * 4 + 2]; p4.w = s2[j4 * 4 + 3];
            *reinterpret_cast<float4*>(&Ps[(r1 + 64) * 68 + e0 + j4 * 4]) = p4;
        }
        __syncthreads();

        // ---- accumulate ctx: a[r][e] += P[r][c] * V[c][e] ----
#pragma unroll 4
        for (int c = 0; c < 64; c++) {
            float p1 = Ps[r1 * 68 + c];
            float p2 = Ps[(r1 + 64) * 68 + c];
#pragma unroll
            for (int j4 = 0; j4 < 4; j4++) {
                float4 v4 = *reinterpret_cast<float4*>(&Vs[c * 64 + e0 + j4 * 4]);
                a1[j4 * 4 + 0] += p1 * v4.x;  a2[j4 * 4 + 0] += p2 * v4.x;
                a1[j4 * 4 + 1] += p1 * v4.y;  a2[j4 * 4 + 1] += p2 * v4.y;
                a1[j4 * 4 + 2] += p1 * v4.z;  a2[j4 * 4 + 2] += p2 * v4.z;
                a1[j4 * 4 + 3] += p1 * v4.w;  a2[j4 * 4 + 3] += p2 * v4.w;
            }
        }
    }

    // Normalize and write ctx as [B, S, H*HD]
    float inv1 = 1.0f / l1;
    float inv2 = 1.0f / l2;
    size_t base1 = ((size_t)b * S_ + m0 + r1) * D_ + h * HD_ + e0;
    size_t base2 = ((size_t)b * S_ + m0 + r1 + 64) * D_ + h * HD_ + e0;
#pragma unroll
    for (int j4 = 0; j4 < 4; j4++) {
        float4 o;
        o.x = a1[j4 * 4 + 0] * inv1; o.y = a1[j4 * 4 + 1] * inv1;
        o.z = a1[j4 * 4 + 2] * inv1; o.w = a1[j4 * 4 + 3] * inv1;
        *reinterpret_cast<float4*>(&g_ctx[base1 + j4 * 4]) = o;
        o.x = a2[j4 * 4 + 0] * inv2; o.y = a2[j4 * 4 + 1] * inv2;
        o.z = a2[j4 * 4 + 2] * inv2; o.w = a2[j4 * 4 + 3] * inv2;
        *reinterpret_cast<float4*>(&g_ctx[base2 + j4 * 4]) = o;
    }
}

// ---------------------------------------------------------------------------
extern "C" void kernel_launch(void* const* d_in, const int* in_sizes, int n_in,
                              void* d_out, int out_size)
{
    const float* x  = (const float*)d_in[0];
    const float* Wq = (const float*)d_in[1];
    const float* bq = (const float*)d_in[2];
    const float* Wk = (const float*)d_in[3];
    const float* bk = (const float*)d_in[4];
    const float* Wv = (const float*)d_in[5];
    const float* bv = (const float*)d_in[6];
    const float* Wp = (const float*)d_in[7];
    const float* bp = (const float*)d_in[8];
    float* out = (float*)d_out;

    cudaFuncSetAttribute(attn_kernel,
                         cudaFuncAttributeMaxDynamicSharedMemorySize, ATTN_SMEM);

    dim3 g1(S_ / 128, B_ * H_, 3);
    qkv_kernel<<<g1, 256>>>(x, Wq, bq, Wk, bk, Wv, bv);

    dim3 g2(S_ / 128, B_ * H_);
    attn_kernel<<<g2, 256, ATTN_SMEM>>>();

    dim3 g3((B_ * S_) / 128, D_ / 64);
    proj_kernel<<<g3, 256>>>(Wp, bp, out);
}

// round 3
// speedup vs baseline: 4.6402x; 4.6402x over previous
#include <cuda_runtime.h>
#include <cuda_bf16.h>
#include <stdint.h>

#define B_  8
#define S_  2048
#define D_  768
#define H_  12
#define HD_ 64
#define BH_ (B_*H_)

typedef __nv_bfloat16 bf16;

// ------------------------- global scratch (no allocs) -----------------------
__device__ __align__(16) bf16 g_xhi [(size_t)B_*S_*D_];
__device__ __align__(16) bf16 g_xlo [(size_t)B_*S_*D_];
__device__ __align__(16) bf16 g_WThi[(size_t)3*H_*HD_*D_];   // [type][h][e_out][d_in]
__device__ __align__(16) bf16 g_WTlo[(size_t)3*H_*HD_*D_];
__device__ __align__(16) bf16 g_WpThi[(size_t)D_*D_];        // [e_out][d_in]
__device__ __align__(16) bf16 g_WpTlo[(size_t)D_*D_];
__device__ __align__(16) bf16 g_Qhi [(size_t)BH_*S_*HD_];
__device__ __align__(16) bf16 g_Qlo [(size_t)BH_*S_*HD_];
__device__ __align__(16) bf16 g_Khi [(size_t)BH_*S_*HD_];
__device__ __align__(16) bf16 g_Klo [(size_t)BH_*S_*HD_];
__device__ __align__(16) bf16 g_VThi[(size_t)BH_*HD_*S_];    // [bh][e][s]
__device__ __align__(16) bf16 g_VTlo[(size_t)BH_*HD_*S_];
__device__ __align__(16) bf16 g_chi [(size_t)B_*S_*D_];
__device__ __align__(16) bf16 g_clo [(size_t)B_*S_*D_];

// ------------------------------- helpers ------------------------------------
__device__ __forceinline__ void splitf(float x, bf16& h, bf16& l) {
    h = __float2bfloat16(x);
    l = __float2bfloat16(x - __bfloat162float(h));
}

__device__ __forceinline__ void split_pack(float a, float b, uint32_t& hi, uint32_t& lo) {
    bf16 ah, al, bh2, bl;
    splitf(a, ah, al);
    splitf(b, bh2, bl);
    __nv_bfloat162 Hh; Hh.x = ah; Hh.y = bh2;
    __nv_bfloat162 Ll; Ll.x = al; Ll.y = bl;
    hi = *reinterpret_cast<uint32_t*>(&Hh);
    lo = *reinterpret_cast<uint32_t*>(&Ll);
}

__device__ __forceinline__ uint32_t ld32(const bf16* p) {
    return *reinterpret_cast<const uint32_t*>(p);
}

// D += A * B  (m16n8k16, bf16 in, f32 acc)
__device__ __forceinline__ void mma4(float* c, const uint32_t* a, uint32_t b0, uint32_t b1) {
    asm volatile(
        "mma.sync.aligned.m16n8k16.row.col.f32.bf16.bf16.f32 "
        "{%0,%1,%2,%3}, {%4,%5,%6,%7}, {%8,%9}, {%0,%1,%2,%3};\n"
        : "+f"(c[0]), "+f"(c[1]), "+f"(c[2]), "+f"(c[3])
        : "r"(a[0]), "r"(a[1]), "r"(a[2]), "r"(a[3]), "r"(b0), "r"(b1));
}

// ------------------------------- prep ---------------------------------------
__global__ void __launch_bounds__(256)
prep_x(const float* __restrict__ x) {
    size_t i4 = (size_t)blockIdx.x * blockDim.x + threadIdx.x;   // float4 index
    if (i4 >= (size_t)B_*S_*D_/4) return;
    float4 v = reinterpret_cast<const float4*>(x)[i4];
    bf16 h0,l0,h1,l1,h2,l2,h3,l3;
    splitf(v.x,h0,l0); splitf(v.y,h1,l1); splitf(v.z,h2,l2); splitf(v.w,h3,l3);
    __nv_bfloat162* dh = reinterpret_cast<__nv_bfloat162*>(g_xhi);
    __nv_bfloat162* dl = reinterpret_cast<__nv_bfloat162*>(g_xlo);
    __nv_bfloat162 a; a.x=h0; a.y=h1; dh[i4*2]   = a;
    a.x=h2; a.y=h3;             dh[i4*2+1] = a;
    a.x=l0; a.y=l1;             dl[i4*2]   = a;
    a.x=l2; a.y=l3;             dl[i4*2+1] = a;
}

__global__ void __launch_bounds__(256)
prep_w(const float* __restrict__ Wq, const float* __restrict__ Wk,
       const float* __restrict__ Wv, const float* __restrict__ Wp) {
    int idx = blockIdx.x * blockDim.x + threadIdx.x;
    const int NW = 3*H_*D_*HD_;
    if (idx < NW) {
        int type = idx / (H_*D_*HD_);
        int rem  = idx % (H_*D_*HD_);
        int h    = rem / (D_*HD_);
        int rem2 = rem % (D_*HD_);
        int d    = rem2 / HD_;
        int e    = rem2 % HD_;
        const float* W = (type==0) ? Wq : (type==1) ? Wk : Wv;
        float v = W[((size_t)h*D_ + d)*HD_ + e];
        bf16 hi, lo; splitf(v, hi, lo);
        size_t dst = ((size_t)(type*H_ + h)*HD_ + e)*D_ + d;
        g_WThi[dst] = hi; g_WTlo[dst] = lo;
    }
    if (idx < D_*D_) {
        int d = idx / D_, e = idx % D_;
        float v = Wp[idx];
        bf16 hi, lo; splitf(v, hi, lo);
        g_WpThi[(size_t)e*D_ + d] = hi;
        g_WpTlo[(size_t)e*D_ + d] = lo;
    }
}

// ------------------------ QKV projection (mma) -------------------------------
// grid (36, S_/128, B_), 256 thr. CTA computes [128 rows x 64 cols] of one
// (type,h) projection. K=768 in chunks of 64. Split-bf16: 3 mmas per product.
#define XS 72
#define VTS 136
#define QKV_SMEM ((128*XS*2 + 64*XS*2) * 2)   // bytes (bf16)

__global__ void __launch_bounds__(256, 2)
qkv_kernel(const float* __restrict__ bq, const float* __restrict__ bk,
           const float* __restrict__ bv) {
    extern __shared__ bf16 dsm[];
    bf16* xs_h = dsm;                 // 128*72
    bf16* xs_l = dsm + 128*XS;
    bf16* ws_h = dsm + 2*128*XS;      // 64*72
    bf16* ws_l = dsm + 2*128*XS + 64*XS;

    const int type = blockIdx.x / H_;
    const int h    = blockIdx.x % H_;
    const int m0   = blockIdx.y * 128;
    const int b    = blockIdx.z;
    const int bh   = b*H_ + h;

    const int t = threadIdx.x, w = t >> 5, lane = t & 31;
    const int g = lane >> 2, q = lane & 3;

    const size_t xbase = (size_t)(b*S_ + m0) * D_;
    const size_t wbase = (size_t)(type*H_ + h) * HD_ * D_;

    float acc[8][4];
#pragma unroll
    for (int nb = 0; nb < 8; nb++)
#pragma unroll
        for (int j = 0; j < 4; j++) acc[nb][j] = 0.0f;

    for (int kc = 0; kc < D_; kc += 64) {
        __syncthreads();
#pragma unroll
        for (int ii = 0; ii < 4; ii++) {               // x tile: 1024 uint4 (128 rows!)
            int i = t + ii*256;
            int r = i >> 3, c8 = i & 7;
            *reinterpret_cast<uint4*>(&xs_h[r*XS + c8*8]) =
                *reinterpret_cast<const uint4*>(&g_xhi[xbase + (size_t)r*D_ + kc + c8*8]);
            *reinterpret_cast<uint4*>(&xs_l[r*XS + c8*8]) =
                *reinterpret_cast<const uint4*>(&g_xlo[xbase + (size_t)r*D_ + kc + c8*8]);
        }
        {                                              // W tile: 256 uint4
            int r = t >> 2, c8 = (t & 3) * 2;
#pragma unroll
            for (int jj = 0; jj < 2; jj++) {
                *reinterpret_cast<uint4*>(&ws_h[r*XS + (c8+jj)*8]) =
                    *reinterpret_cast<const uint4*>(&g_WThi[wbase + (size_t)r*D_ + kc + (c8+jj)*8]);
                *reinterpret_cast<uint4*>(&ws_l[r*XS + (c8+jj)*8]) =
                    *reinterpret_cast<const uint4*>(&g_WTlo[wbase + (size_t)r*D_ + kc + (c8+jj)*8]);
            }
        }
        __syncthreads();

#pragma unroll
        for (int ks = 0; ks < 4; ks++) {
            const int ar = w*16 + g;
            uint32_t ah[4], al[4];
            ah[0] = ld32(&xs_h[(ar  )*XS + ks*16 + 2*q]);
            ah[1] = ld32(&xs_h[(ar+8)*XS + ks*16 + 2*q]);
            ah[2] = ld32(&xs_h[(ar  )*XS + ks*16 + 8 + 2*q]);
            ah[3] = ld32(&xs_h[(ar+8)*XS + ks*16 + 8 + 2*q]);
            al[0] = ld32(&xs_l[(ar  )*XS + ks*16 + 2*q]);
            al[1] = ld32(&xs_l[(ar+8)*XS + ks*16 + 2*q]);
            al[2] = ld32(&xs_l[(ar  )*XS + ks*16 + 8 + 2*q]);
            al[3] = ld32(&xs_l[(ar+8)*XS + ks*16 + 8 + 2*q]);
#pragma unroll
            for (int nb = 0; nb < 8; nb++) {
                uint32_t bh0 = ld32(&ws_h[(nb*8+g)*XS + ks*16 + 2*q]);
                uint32_t bh1 = ld32(&ws_h[(nb*8+g)*XS + ks*16 + 8 + 2*q]);
                uint32_t bl0 = ld32(&ws_l[(nb*8+g)*XS + ks*16 + 2*q]);
                uint32_t bl1 = ld32(&ws_l[(nb*8+g)*XS + ks*16 + 8 + 2*q]);
                mma4(acc[nb], ah, bh0, bh1);
                mma4(acc[nb], ah, bl0, bl1);
                mma4(acc[nb], al, bh0, bh1);
            }
        }
    }

    // epilogue: bias (+ scale for Q), split, store
    const float* bias = (type==0) ? bq : (type==1) ? bk : bv;
    const float rscale = 1.0f / (8.0f + 1e-6f);
    const int lr = w*16 + g;                  // local row
#pragma unroll
    for (int nb = 0; nb < 8; nb++) {
        int col = nb*8 + 2*q;
        float b0 = bias[h*HD_ + col], b1 = bias[h*HD_ + col + 1];
        acc[nb][0] += b0; acc[nb][1] += b1;
        acc[nb][2] += b0; acc[nb][3] += b1;
        if (type == 0) {
            acc[nb][0] *= rscale; acc[nb][1] *= rscale;
            acc[nb][2] *= rscale; acc[nb][3] *= rscale;
        }
    }

    if (type < 2) {
        bf16* dh = (type==0) ? g_Qhi : g_Khi;
        bf16* dl = (type==0) ? g_Qlo : g_Klo;
        size_t obase = (size_t)bh * S_ * HD_;
#pragma unroll
        for (int nb = 0; nb < 8; nb++) {
            int col = nb*8 + 2*q;
#pragma unroll
            for (int rr = 0; rr < 2; rr++) {
                int grow = m0 + lr + rr*8;
                bf16 h0,l0,h1,l1;
                splitf(acc[nb][rr*2+0], h0, l0);
                splitf(acc[nb][rr*2+1], h1, l1);
                __nv_bfloat162 ph; ph.x=h0; ph.y=h1;
                __nv_bfloat162 pl; pl.x=l0; pl.y=l1;
                *reinterpret_cast<__nv_bfloat162*>(&dh[obase + (size_t)grow*HD_ + col]) = ph;
                *reinterpret_cast<__nv_bfloat162*>(&dl[obase + (size_t)grow*HD_ + col]) = pl;
            }
        }
    } else {
        // V: transpose through smem -> g_VT[bh][e][s]
        bf16* vt = dsm;                       // 64 x 136
        size_t obase = (size_t)bh * HD_ * S_;
#pragma unroll
        for (int p = 0; p < 2; p++) {
            __syncthreads();
#pragma unroll
            for (int nb = 0; nb < 8; nb++) {
                int col = nb*8 + 2*q;
#pragma unroll
                for (int rr = 0; rr < 2; rr++) {
                    int r = lr + rr*8;
                    bf16 h0,l0,h1,l1;
                    splitf(acc[nb][rr*2+0], h0, l0);
                    splitf(acc[nb][rr*2+1], h1, l1);
                    vt[(col  )*VTS + r] = p ? l0 : h0;
                    vt[(col+1)*VTS + r] = p ? l1 : h1;
                }
            }
            __syncthreads();
            bf16* dst = p ? g_VTlo : g_VThi;
#pragma unroll
            for (int ii = 0; ii < 4; ii++) {          // 1024 uint4
                int i = t + ii*256;
                int col = i >> 4, r8 = i & 15;
                *reinterpret_cast<uint4*>(&dst[obase + (size_t)col*S_ + m0 + r8*8]) =
                    *reinterpret_cast<uint4*>(&vt[col*VTS + r8*8]);
            }
        }
    }
}

// ------------------------- flash attention (mma) -----------------------------
// grid (16, 96), 256 thr, warp w owns q-rows [16w,16w+16). 64-key tiles.
__global__ void __launch_bounds__(256, 2)
attn_kernel() {
    __shared__ bf16 Khs[64*XS], Kls[64*XS], Vhs[64*XS], Vls[64*XS];

    const int bh = blockIdx.y;
    const int m0 = blockIdx.x * 128;
    const int t = threadIdx.x, w = t >> 5, lane = t & 31;
    const int g = lane >> 2, q = lane & 3;
    const int lr = w*16 + g;

    const size_t qkbase = (size_t)bh * S_ * HD_;
    const size_t vbase  = (size_t)bh * HD_ * S_;

    // Q fragments in registers (reused across all key tiles)
    uint32_t qh[4][4], ql[4][4];
#pragma unroll
    for (int ks = 0; ks < 4; ks++) {
        qh[ks][0] = ld32(&g_Qhi[qkbase + (size_t)(m0+lr  )*HD_ + ks*16 + 2*q]);
        qh[ks][1] = ld32(&g_Qhi[qkbase + (size_t)(m0+lr+8)*HD_ + ks*16 + 2*q]);
        qh[ks][2] = ld32(&g_Qhi[qkbase + (size_t)(m0+lr  )*HD_ + ks*16 + 8 + 2*q]);
        qh[ks][3] = ld32(&g_Qhi[qkbase + (size_t)(m0+lr+8)*HD_ + ks*16 + 8 + 2*q]);
        ql[ks][0] = ld32(&g_Qlo[qkbase + (size_t)(m0+lr  )*HD_ + ks*16 + 2*q]);
        ql[ks][1] = ld32(&g_Qlo[qkbase + (size_t)(m0+lr+8)*HD_ + ks*16 + 2*q]);
        ql[ks][2] = ld32(&g_Qlo[qkbase + (size_t)(m0+lr  )*HD_ + ks*16 + 8 + 2*q]);
        ql[ks][3] = ld32(&g_Qlo[qkbase + (size_t)(m0+lr+8)*HD_ + ks*16 + 8 + 2*q]);
    }

    float m1 = -1e30f, m2 = -1e30f, l1 = 0.0f, l2 = 0.0f;
    float o[8][4];
#pragma unroll
    for (int nb = 0; nb < 8; nb++)
#pragma unroll
        for (int j = 0; j < 4; j++) o[nb][j] = 0.0f;

    for (int n0 = 0; n0 < S_; n0 += 64) {
        __syncthreads();
#pragma unroll
        for (int ii = 0; ii < 2; ii++) {          // 512 uint4 per buffer (64 rows)
            int i = t + ii*256;
            int r = i >> 3, c8 = i & 7;
            *reinterpret_cast<uint4*>(&Khs[r*XS + c8*8]) =
                *reinterpret_cast<const uint4*>(&g_Khi[qkbase + (size_t)(n0+r)*HD_ + c8*8]);
            *reinterpret_cast<uint4*>(&Kls[r*XS + c8*8]) =
                *reinterpret_cast<const uint4*>(&g_Klo[qkbase + (size_t)(n0+r)*HD_ + c8*8]);
            *reinterpret_cast<uint4*>(&Vhs[r*XS + c8*8]) =
                *reinterpret_cast<const uint4*>(&g_VThi[vbase + (size_t)r*S_ + n0 + c8*8]);
            *reinterpret_cast<uint4*>(&Vls[r*XS + c8*8]) =
                *reinterpret_cast<const uint4*>(&g_VTlo[vbase + (size_t)r*S_ + n0 + c8*8]);
        }
        __syncthreads();

        // ---- S = Q K^T ----
        float s[8][4];
#pragma unroll
        for (int nb = 0; nb < 8; nb++)
#pragma unroll
            for (int j = 0; j < 4; j++) s[nb][j] = 0.0f;

#pragma unroll
        for (int ks = 0; ks < 4; ks++) {
#pragma unroll
            for (int nb = 0; nb < 8; nb++) {
                uint32_t kb0 = ld32(&Khs[(nb*8+g)*XS + ks*16 + 2*q]);
                uint32_t kb1 = ld32(&Khs[(nb*8+g)*XS + ks*16 + 8 + 2*q]);
                uint32_t kl0 = ld32(&Kls[(nb*8+g)*XS + ks*16 + 2*q]);
                uint32_t kl1 = ld32(&Kls[(nb*8+g)*XS + ks*16 + 8 + 2*q]);
                mma4(s[nb], qh[ks], kb0, kb1);
                mma4(s[nb], qh[ks], kl0, kl1);
                mma4(s[nb], ql[ks], kb0, kb1);
            }
        }

        // ---- online softmax (rows lr and lr+8; quad lanes share a row) ----
        float tm1 = -1e30f, tm2 = -1e30f;
#pragma unroll
        for (int nb = 0; nb < 8; nb++) {
            tm1 = fmaxf(tm1, fmaxf(s[nb][0], s[nb][1]));
            tm2 = fmaxf(tm2, fmaxf(s[nb][2], s[nb][3]));
        }
        tm1 = fmaxf(tm1, __shfl_xor_sync(0xffffffffu, tm1, 1));
        tm1 = fmaxf(tm1, __shfl_xor_sync(0xffffffffu, tm1, 2));
        tm2 = fmaxf(tm2, __shfl_xor_sync(0xffffffffu, tm2, 1));
        tm2 = fmaxf(tm2, __shfl_xor_sync(0xffffffffu, tm2, 2));

        float mn1 = fmaxf(m1, tm1), mn2 = fmaxf(m2, tm2);
        float c1f = __expf(m1 - mn1), c2f = __expf(m2 - mn2);

        float sum1 = 0.0f, sum2 = 0.0f;
#pragma unroll
        for (int nb = 0; nb < 8; nb++) {
            s[nb][0] = __expf(s[nb][0] - mn1);
            s[nb][1] = __expf(s[nb][1] - mn1);
            s[nb][2] = __expf(s[nb][2] - mn2);
            s[nb][3] = __expf(s[nb][3] - mn2);
            sum1 += s[nb][0] + s[nb][1];
            sum2 += s[nb][2] + s[nb][3];
        }
        sum1 += __shfl_xor_sync(0xffffffffu, sum1, 1);
        sum1 += __shfl_xor_sync(0xffffffffu, sum1, 2);
        sum2 += __shfl_xor_sync(0xffffffffu, sum2, 1);
        sum2 += __shfl_xor_sync(0xffffffffu, sum2, 2);

        l1 = l1 * c1f + sum1;  m1 = mn1;
        l2 = l2 * c2f + sum2;  m2 = mn2;
#pragma unroll
        for (int nb = 0; nb < 8; nb++) {
            o[nb][0] *= c1f; o[nb][1] *= c1f;
            o[nb][2] *= c2f; o[nb][3] *= c2f;
        }

        // ---- ctx += P V  (P: D-frag -> A-frag in registers) ----
#pragma unroll
        for (int j = 0; j < 4; j++) {           // k-step over keys
            uint32_t pa_h[4], pa_l[4];
            split_pack(s[2*j  ][0], s[2*j  ][1], pa_h[0], pa_l[0]);
            split_pack(s[2*j  ][2], s[2*j  ][3], pa_h[1], pa_l[1]);
            split_pack(s[2*j+1][0], s[2*j+1][1], pa_h[2], pa_l[2]);
            split_pack(s[2*j+1][2], s[2*j+1][3], pa_h[3], pa_l[3]);
#pragma unroll
            for (int nb = 0; nb < 8; nb++) {
                uint32_t vh0 = ld32(&Vhs[(nb*8+g)*XS + j*16 + 2*q]);
                uint32_t vh1 = ld32(&Vhs[(nb*8+g)*XS + j*16 + 8 + 2*q]);
                uint32_t vl0 = ld32(&Vls[(nb*8+g)*XS + j*16 + 2*q]);
                uint32_t vl1 = ld32(&Vls[(nb*8+g)*XS + j*16 + 8 + 2*q]);
                mma4(o[nb], pa_h, vh0, vh1);
                mma4(o[nb], pa_h, vl0, vl1);
                mma4(o[nb], pa_l, vh0, vh1);
            }
        }
    }

    // ---- epilogue: normalize, split, store ctx as [b, s, h*64+e] ----
    float inv1 = 1.0f / l1, inv2 = 1.0f / l2;
    int b = bh / H_, h = bh % H_;
#pragma unroll
    for (int nb = 0; nb < 8; nb++) {
        int col = h*HD_ + nb*8 + 2*q;
        float v00 = o[nb][0]*inv1, v01 = o[nb][1]*inv1;
        float v10 = o[nb][2]*inv2, v11 = o[nb][3]*inv2;
        size_t r1 = ((size_t)b*S_ + m0 + lr    ) * D_ + col;
        size_t r2 = ((size_t)b*S_ + m0 + lr + 8) * D_ + col;
        bf16 h0,l0,h1,l1b;
        splitf(v00,h0,l0); splitf(v01,h1,l1b);
        __nv_bfloat162 ph; ph.x=h0; ph.y=h1;
        __nv_bfloat162 pl; pl.x=l0; pl.y=l1b;
        *reinterpret_cast<__nv_bfloat162*>(&g_chi[r1]) = ph;
        *reinterpret_cast<__nv_bfloat162*>(&g_clo[r1]) = pl;
        splitf(v10,h0,l0); splitf(v11,h1,l1b);
        ph.x=h0; ph.y=h1; pl.x=l0; pl.y=l1b;
        *reinterpret_cast<__nv_bfloat162*>(&g_chi[r2]) = ph;
        *reinterpret_cast<__nv_bfloat162*>(&g_clo[r2]) = pl;
    }
}

// --------------------------- output projection -------------------------------
// grid (12, 128): n-tile fastest for A-tile L2 reuse. Tile 128x64, K=768.
__global__ void __launch_bounds__(256, 2)
proj_kernel(const float* __restrict__ bp, float* __restrict__ out) {
    extern __shared__ bf16 dsm[];
    bf16* xs_h = dsm;
    bf16* xs_l = dsm + 128*XS;
    bf16* ws_h = dsm + 2*128*XS;
    bf16* ws_l = dsm + 2*128*XS + 64*XS;

    const int n0 = blockIdx.x * 64;
    const int m0 = blockIdx.y * 128;
    const int t = threadIdx.x, w = t >> 5, lane = t & 31;
    const int g = lane >> 2, q = lane & 3;

    float acc[8][4];
#pragma unroll
    for (int nb = 0; nb < 8; nb++)
#pragma unroll
        for (int j = 0; j < 4; j++) acc[nb][j] = 0.0f;

    for (int kc = 0; kc < D_; kc += 64) {
        __syncthreads();
#pragma unroll
        for (int ii = 0; ii < 4; ii++) {              // 1024 uint4 (128 rows!)
            int i = t + ii*256;
            int r = i >> 3, c8 = i & 7;
            *reinterpret_cast<uint4*>(&xs_h[r*XS + c8*8]) =
                *reinterpret_cast<const uint4*>(&g_chi[(size_t)(m0+r)*D_ + kc + c8*8]);
            *reinterpret_cast<uint4*>(&xs_l[r*XS + c8*8]) =
                *reinterpret_cast<const uint4*>(&g_clo[(size_t)(m0+r)*D_ + kc + c8*8]);
        }
        {
            int r = t >> 2, c8 = (t & 3) * 2;
#pragma unroll
            for (int jj = 0; jj < 2; jj++) {
                *reinterpret_cast<uint4*>(&ws_h[r*XS + (c8+jj)*8]) =
                    *reinterpret_cast<const uint4*>(&g_WpThi[(size_t)(n0+r)*D_ + kc + (c8+jj)*8]);
                *reinterpret_cast<uint4*>(&ws_l[r*XS + (c8+jj)*8]) =
                    *reinterpret_cast<const uint4*>(&g_WpTlo[(size_t)(n0+r)*D_ + kc + (c8+jj)*8]);
            }
        }
        __syncthreads();

#pragma unroll
        for (int ks = 0; ks < 4; ks++) {
            const int ar = w*16 + g;
            uint32_t ah[4], al[4];
            ah[0] = ld32(&xs_h[(ar  )*XS + ks*16 + 2*q]);
            ah[1] = ld32(&xs_h[(ar+8)*XS + ks*16 + 2*q]);
            ah[2] = ld32(&xs_h[(ar  )*XS + ks*16 + 8 + 2*q]);
            ah[3] = ld32(&xs_h[(ar+8)*XS + ks*16 + 8 + 2*q]);
            al[0] = ld32(&xs_l[(ar  )*XS + ks*16 + 2*q]);
            al[1] = ld32(&xs_l[(ar+8)*XS + ks*16 + 2*q]);
            al[2] = ld32(&xs_l[(ar  )*XS + ks*16 + 8 + 2*q]);
            al[3] = ld32(&xs_l[(ar+8)*XS + ks*16 + 8 + 2*q]);
#pragma unroll
            for (int nb = 0; nb < 8; nb++) {
                uint32_t bh0 = ld32(&ws_h[(nb*8+g)*XS + ks*16 + 2*q]);
                uint32_t bh1 = ld32(&ws_h[(nb*8+g)*XS + ks*16 + 8 + 2*q]);
                uint32_t bl0 = ld32(&ws_l[(nb*8+g)*XS + ks*16 + 2*q]);
                uint32_t bl1 = ld32(&ws_l[(nb*8+g)*XS + ks*16 + 8 + 2*q]);
                mma4(acc[nb], ah, bh0, bh1);
                mma4(acc[nb], ah, bl0, bl1);
                mma4(acc[nb], al, bh0, bh1);
            }
        }
    }

    const int lr = w*16 + g;
#pragma unroll
    for (int nb = 0; nb < 8; nb++) {
        int col = n0 + nb*8 + 2*q;
        float b0 = bp[col], b1 = bp[col+1];
        float2 v0 = make_float2(acc[nb][0] + b0, acc[nb][1] + b1);
        float2 v1 = make_float2(acc[nb][2] + b0, acc[nb][3] + b1);
        *reinterpret_cast<float2*>(&out[(size_t)(m0 + lr    )*D_ + col]) = v0;
        *reinterpret_cast<float2*>(&out[(size_t)(m0 + lr + 8)*D_ + col]) = v1;
    }
}

// -----------------------------------------------------------------------------
extern "C" void kernel_launch(void* const* d_in, const int* in_sizes, int n_in,
                              void* d_out, int out_size)
{
    const float* x  = (const float*)d_in[0];
    const float* Wq = (const float*)d_in[1];
    const float* bq = (const float*)d_in[2];
    const float* Wk = (const float*)d_in[3];
    const float* bk = (const float*)d_in[4];
    const float* Wv = (const float*)d_in[5];
    const float* bv = (const float*)d_in[6];
    const float* Wp = (const float*)d_in[7];
    const float* bp = (const float*)d_in[8];
    float* out = (float*)d_out;

    cudaFuncSetAttribute(qkv_kernel,  cudaFuncAttributeMaxDynamicSharedMemorySize, QKV_SMEM);
    cudaFuncSetAttribute(proj_kernel, cudaFuncAttributeMaxDynamicSharedMemorySize, QKV_SMEM);

    prep_x<<<(B_*S_*D_/4 + 255)/256, 256>>>(x);
    prep_w<<<(3*H_*D_*HD_ + 255)/256, 256>>>(Wq, Wk, Wv, Wp);

    qkv_kernel<<<dim3(3*H_, S_/128, B_), 256, QKV_SMEM>>>(bq, bk, bv);
    attn_kernel<<<dim3(S_/128, BH_), 256>>>();
    proj_kernel<<<dim3(D_/64, (B_*S_)/128), 256, QKV_SMEM>>>(bp, out);
}

// round 10
// speedup vs baseline: 4.6636x; 1.0050x over previous
#include <cuda_runtime.h>
#include <cuda_bf16.h>
#include <stdint.h>

#define B_  8
#define S_  2048
#define D_  768
#define H_  12
#define HD_ 64
#define BH_ (B_*H_)

typedef __nv_bfloat16 bf16;

// ------------------------- global scratch (no allocs) -----------------------
__device__ __align__(16) bf16 g_xhi [(size_t)B_*S_*D_];
__device__ __align__(16) bf16 g_xlo [(size_t)B_*S_*D_];
__device__ __align__(16) bf16 g_WThi[(size_t)3*H_*HD_*D_];   // [type][h][e_out][d_in]
__device__ __align__(16) bf16 g_WTlo[(size_t)3*H_*HD_*D_];
__device__ __align__(16) bf16 g_WpThi[(size_t)D_*D_];        // [e_out][d_in]
__device__ __align__(16) bf16 g_WpTlo[(size_t)D_*D_];
__device__ __align__(16) bf16 g_Qhi [(size_t)BH_*S_*HD_];
__device__ __align__(16) bf16 g_Qlo [(size_t)BH_*S_*HD_];
__device__ __align__(16) bf16 g_Khi [(size_t)BH_*S_*HD_];
__device__ __align__(16) bf16 g_Klo [(size_t)BH_*S_*HD_];
__device__ __align__(16) bf16 g_VThi[(size_t)BH_*HD_*S_];    // [bh][e][s]
__device__ __align__(16) bf16 g_VTlo[(size_t)BH_*HD_*S_];
__device__ __align__(16) bf16 g_chi [(size_t)B_*S_*D_];
__device__ __align__(16) bf16 g_clo [(size_t)B_*S_*D_];

// ------------------------------- helpers ------------------------------------
__device__ __forceinline__ void splitf(float x, bf16& h, bf16& l) {
    h = __float2bfloat16(x);
    l = __float2bfloat16(x - __bfloat162float(h));
}

__device__ __forceinline__ void split_pack(float a, float b, uint32_t& hi, uint32_t& lo) {
    bf16 ah, al, bh2, bl;
    splitf(a, ah, al);
    splitf(b, bh2, bl);
    __nv_bfloat162 Hh; Hh.x = ah; Hh.y = bh2;
    __nv_bfloat162 Ll; Ll.x = al; Ll.y = bl;
    hi = *reinterpret_cast<uint32_t*>(&Hh);
    lo = *reinterpret_cast<uint32_t*>(&Ll);
}

__device__ __forceinline__ uint32_t ld32(const bf16* p) {
    return *reinterpret_cast<const uint32_t*>(p);
}

__device__ __forceinline__ uint32_t smem_u32(const void* p) {
    uint32_t a;
    asm("{ .reg .u64 t; cvta.to.shared.u64 t, %1; cvt.u32.u64 %0, t; }"
        : "=r"(a) : "l"(p));
    return a;
}

__device__ __forceinline__ void cpa16(uint32_t dst, const void* src) {
    asm volatile("cp.async.cg.shared.global [%0], [%1], 16;"
                 :: "r"(dst), "l"(src) : "memory");
}
#define CP_COMMIT() asm volatile("cp.async.commit_group;" ::: "memory")
#define CP_WAIT(n)  asm volatile("cp.async.wait_group %0;" :: "n"(n) : "memory")

// D += A * B  (m16n8k16, bf16 in, f32 acc)
__device__ __forceinline__ void mma4(float* c, const uint32_t* a, uint32_t b0, uint32_t b1) {
    asm volatile(
        "mma.sync.aligned.m16n8k16.row.col.f32.bf16.bf16.f32 "
        "{%0,%1,%2,%3}, {%4,%5,%6,%7}, {%8,%9}, {%0,%1,%2,%3};\n"
        : "+f"(c[0]), "+f"(c[1]), "+f"(c[2]), "+f"(c[3])
        : "r"(a[0]), "r"(a[1]), "r"(a[2]), "r"(a[3]), "r"(b0), "r"(b1));
}

// ------------------------------- prep ---------------------------------------
__global__ void __launch_bounds__(256)
prep_x(const float* __restrict__ x) {
    size_t i4 = (size_t)blockIdx.x * blockDim.x + threadIdx.x;
    if (i4 >= (size_t)B_*S_*D_/4) return;
    float4 v = reinterpret_cast<const float4*>(x)[i4];
    bf16 h0,l0,h1,l1,h2,l2,h3,l3;
    splitf(v.x,h0,l0); splitf(v.y,h1,l1); splitf(v.z,h2,l2); splitf(v.w,h3,l3);
    __nv_bfloat162* dh = reinterpret_cast<__nv_bfloat162*>(g_xhi);
    __nv_bfloat162* dl = reinterpret_cast<__nv_bfloat162*>(g_xlo);
    __nv_bfloat162 a; a.x=h0; a.y=h1; dh[i4*2]   = a;
    a.x=h2; a.y=h3;             dh[i4*2+1] = a;
    a.x=l0; a.y=l1;             dl[i4*2]   = a;
    a.x=l2; a.y=l3;             dl[i4*2+1] = a;
}

__global__ void __launch_bounds__(256)
prep_w(const float* __restrict__ Wq, const float* __restrict__ Wk,
       const float* __restrict__ Wv, const float* __restrict__ Wp) {
    int idx = blockIdx.x * blockDim.x + threadIdx.x;
    const int NW = 3*H_*D_*HD_;
    if (idx < NW) {
        int type = idx / (H_*D_*HD_);
        int rem  = idx % (H_*D_*HD_);
        int h    = rem / (D_*HD_);
        int rem2 = rem % (D_*HD_);
        int d    = rem2 / HD_;
        int e    = rem2 % HD_;
        const float* W = (type==0) ? Wq : (type==1) ? Wk : Wv;
        float v = W[((size_t)h*D_ + d)*HD_ + e];
        bf16 hi, lo; splitf(v, hi, lo);
        size_t dst = ((size_t)(type*H_ + h)*HD_ + e)*D_ + d;
        g_WThi[dst] = hi; g_WTlo[dst] = lo;
    }
    if (idx < D_*D_) {
        int d = idx / D_, e = idx % D_;
        float v = Wp[idx];
        bf16 hi, lo; splitf(v, hi, lo);
        g_WpThi[(size_t)e*D_ + d] = hi;
        g_WpTlo[(size_t)e*D_ + d] = lo;
    }
}

// ------------------------ QKV projection (mma) -------------------------------
#define XS 72
#define VTS 136
#define QKV_SMEM ((128*XS*2 + 64*XS*2) * 2)   // bytes (bf16)

__global__ void __launch_bounds__(256, 2)
qkv_kernel(const float* __restrict__ bq, const float* __restrict__ bk,
           const float* __restrict__ bv) {
    extern __shared__ bf16 dsm[];
    bf16* xs_h = dsm;                 // 128*72
    bf16* xs_l = dsm + 128*XS;
    bf16* ws_h = dsm + 2*128*XS;      // 64*72
    bf16* ws_l = dsm + 2*128*XS + 64*XS;

    const int type = blockIdx.x / H_;
    const int h    = blockIdx.x % H_;
    const int m0   = blockIdx.y * 128;
    const int b    = blockIdx.z;
    const int bh   = b*H_ + h;

    const int t = threadIdx.x, w = t >> 5, lane = t & 31;
    const int g = lane >> 2, q = lane & 3;

    const size_t xbase = (size_t)(b*S_ + m0) * D_;
    const size_t wbase = (size_t)(type*H_ + h) * HD_ * D_;

    float acc[8][4];
#pragma unroll
    for (int nb = 0; nb < 8; nb++)
#pragma unroll
        for (int j = 0; j < 4; j++) acc[nb][j] = 0.0f;

    for (int kc = 0; kc < D_; kc += 64) {
        __syncthreads();
#pragma unroll
        for (int ii = 0; ii < 4; ii++) {               // x tile: 1024 uint4
            int i = t + ii*256;
            int r = i >> 3, c8 = i & 7;
            *reinterpret_cast<uint4*>(&xs_h[r*XS + c8*8]) =
                *reinterpret_cast<const uint4*>(&g_xhi[xbase + (size_t)r*D_ + kc + c8*8]);
            *reinterpret_cast<uint4*>(&xs_l[r*XS + c8*8]) =
                *reinterpret_cast<const uint4*>(&g_xlo[xbase + (size_t)r*D_ + kc + c8*8]);
        }
        {                                              // W tile: 256 uint4
            int r = t >> 2, c8 = (t & 3) * 2;
#pragma unroll
            for (int jj = 0; jj < 2; jj++) {
                *reinterpret_cast<uint4*>(&ws_h[r*XS + (c8+jj)*8]) =
                    *reinterpret_cast<const uint4*>(&g_WThi[wbase + (size_t)r*D_ + kc + (c8+jj)*8]);
                *reinterpret_cast<uint4*>(&ws_l[r*XS + (c8+jj)*8]) =
                    *reinterpret_cast<const uint4*>(&g_WTlo[wbase + (size_t)r*D_ + kc + (c8+jj)*8]);
            }
        }
        __syncthreads();

#pragma unroll
        for (int ks = 0; ks < 4; ks++) {
            const int ar = w*16 + g;
            uint32_t ah[4], al[4];
            ah[0] = ld32(&xs_h[(ar  )*XS + ks*16 + 2*q]);
            ah[1] = ld32(&xs_h[(ar+8)*XS + ks*16 + 2*q]);
            ah[2] = ld32(&xs_h[(ar  )*XS + ks*16 + 8 + 2*q]);
            ah[3] = ld32(&xs_h[(ar+8)*XS + ks*16 + 8 + 2*q]);
            al[0] = ld32(&xs_l[(ar  )*XS + ks*16 + 2*q]);
            al[1] = ld32(&xs_l[(ar+8)*XS + ks*16 + 2*q]);
            al[2] = ld32(&xs_l[(ar  )*XS + ks*16 + 8 + 2*q]);
            al[3] = ld32(&xs_l[(ar+8)*XS + ks*16 + 8 + 2*q]);
#pragma unroll
            for (int nb = 0; nb < 8; nb++) {
                uint32_t bh0 = ld32(&ws_h[(nb*8+g)*XS + ks*16 + 2*q]);
                uint32_t bh1 = ld32(&ws_h[(nb*8+g)*XS + ks*16 + 8 + 2*q]);
                uint32_t bl0 = ld32(&ws_l[(nb*8+g)*XS + ks*16 + 2*q]);
                uint32_t bl1 = ld32(&ws_l[(nb*8+g)*XS + ks*16 + 8 + 2*q]);
                mma4(acc[nb], ah, bh0, bh1);
                mma4(acc[nb], ah, bl0, bl1);
                mma4(acc[nb], al, bh0, bh1);
            }
        }
    }

    const float* bias = (type==0) ? bq : (type==1) ? bk : bv;
    const float rscale = 1.0f / (8.0f + 1e-6f);
    const int lr = w*16 + g;
#pragma unroll
    for (int nb = 0; nb < 8; nb++) {
        int col = nb*8 + 2*q;
        float b0 = bias[h*HD_ + col], b1 = bias[h*HD_ + col + 1];
        acc[nb][0] += b0; acc[nb][1] += b1;
        acc[nb][2] += b0; acc[nb][3] += b1;
        if (type == 0) {
            acc[nb][0] *= rscale; acc[nb][1] *= rscale;
            acc[nb][2] *= rscale; acc[nb][3] *= rscale;
        }
    }

    if (type < 2) {
        bf16* dh = (type==0) ? g_Qhi : g_Khi;
        bf16* dl = (type==0) ? g_Qlo : g_Klo;
        size_t obase = (size_t)bh * S_ * HD_;
#pragma unroll
        for (int nb = 0; nb < 8; nb++) {
            int col = nb*8 + 2*q;
#pragma unroll
            for (int rr = 0; rr < 2; rr++) {
                int grow = m0 + lr + rr*8;
                bf16 h0,l0,h1,l1;
                splitf(acc[nb][rr*2+0], h0, l0);
                splitf(acc[nb][rr*2+1], h1, l1);
                __nv_bfloat162 ph; ph.x=h0; ph.y=h1;
                __nv_bfloat162 pl; pl.x=l0; pl.y=l1;
                *reinterpret_cast<__nv_bfloat162*>(&dh[obase + (size_t)grow*HD_ + col]) = ph;
                *reinterpret_cast<__nv_bfloat162*>(&dl[obase + (size_t)grow*HD_ + col]) = pl;
            }
        }
    } else {
        bf16* vt = dsm;                       // 64 x 136
        size_t obase = (size_t)bh * HD_ * S_;
#pragma unroll
        for (int p = 0; p < 2; p++) {
            __syncthreads();
#pragma unroll
            for (int nb = 0; nb < 8; nb++) {
                int col = nb*8 + 2*q;
#pragma unroll
                for (int rr = 0; rr < 2; rr++) {
                    int r = lr + rr*8;
                    bf16 h0,l0,h1,l1;
                    splitf(acc[nb][rr*2+0], h0, l0);
                    splitf(acc[nb][rr*2+1], h1, l1);
                    vt[(col  )*VTS + r] = p ? l0 : h0;
                    vt[(col+1)*VTS + r] = p ? l1 : h1;
                }
            }
            __syncthreads();
            bf16* dst = p ? g_VTlo : g_VThi;
#pragma unroll
            for (int ii = 0; ii < 4; ii++) {          // 1024 uint4
                int i = t + ii*256;
                int col = i >> 4, r8 = i & 15;
                *reinterpret_cast<uint4*>(&dst[obase + (size_t)col*S_ + m0 + r8*8]) =
                    *reinterpret_cast<uint4*>(&vt[col*VTS + r8*8]);
            }
        }
    }
}

// ------------------ flash attention (mma.sync + cp.async) --------------------
// Double-buffered K/V stages; cp.async prefetch of tile t+1 overlaps compute t.
#define STG_ELEMS (4*64*XS)                 // bf16 elems per stage (K hi/lo, V hi/lo)
#define ATTN_DSMEM (2*STG_ELEMS*2)          // bytes = 73728

__global__ void __launch_bounds__(256, 2)
attn_kernel() {
    extern __shared__ bf16 smA[];
    const uint32_t smb = smem_u32(smA);

    const int bh = blockIdx.y;
    const int m0 = blockIdx.x * 128;
    const int t = threadIdx.x, w = t >> 5, lane = t & 31;
    const int g = lane >> 2, q = lane & 3;
    const int lr = w*16 + g;

    const size_t qkbase = (size_t)bh * S_ * HD_;
    const size_t vbase  = (size_t)bh * HD_ * S_;

    // Q fragments in registers (reused across all key tiles)
    uint32_t qh[4][4], ql[4][4];
#pragma unroll
    for (int ks = 0; ks < 4; ks++) {
        qh[ks][0] = ld32(&g_Qhi[qkbase + (size_t)(m0+lr  )*HD_ + ks*16 + 2*q]);
        qh[ks][1] = ld32(&g_Qhi[qkbase + (size_t)(m0+lr+8)*HD_ + ks*16 + 2*q]);
        qh[ks][2] = ld32(&g_Qhi[qkbase + (size_t)(m0+lr  )*HD_ + ks*16 + 8 + 2*q]);
        qh[ks][3] = ld32(&g_Qhi[qkbase + (size_t)(m0+lr+8)*HD_ + ks*16 + 8 + 2*q]);
        ql[ks][0] = ld32(&g_Qlo[qkbase + (size_t)(m0+lr  )*HD_ + ks*16 + 2*q]);
        ql[ks][1] = ld32(&g_Qlo[qkbase + (size_t)(m0+lr+8)*HD_ + ks*16 + 2*q]);
        ql[ks][2] = ld32(&g_Qlo[qkbase + (size_t)(m0+lr  )*HD_ + ks*16 + 8 + 2*q]);
        ql[ks][3] = ld32(&g_Qlo[qkbase + (size_t)(m0+lr+8)*HD_ + ks*16 + 8 + 2*q]);
    }

    float m1 = -1e30f, m2 = -1e30f, l1 = 0.0f, l2 = 0.0f;
    float o[8][4];
#pragma unroll
    for (int nb = 0; nb < 8; nb++)
#pragma unroll
        for (int j = 0; j < 4; j++) o[nb][j] = 0.0f;

    // cp.async issue of one 64-key tile into stage st (8 cpa16 per thread)
    auto issue = [&](int n0, int st) {
        uint32_t sb = smb + (uint32_t)st * STG_ELEMS * 2;
#pragma unroll
        for (int ii = 0; ii < 2; ii++) {
            int i = t + ii*256;
            int r = i >> 3, c8 = i & 7;
            uint32_t ro = (uint32_t)(r*XS + c8*8) * 2;
            cpa16(sb + 0*64*XS*2 + ro, &g_Khi [qkbase + (size_t)(n0+r)*HD_ + c8*8]);
            cpa16(sb + 1*64*XS*2 + ro, &g_Klo [qkbase + (size_t)(n0+r)*HD_ + c8*8]);
            cpa16(sb + 2*64*XS*2 + ro, &g_VThi[vbase  + (size_t)r*S_ + n0 + c8*8]);
            cpa16(sb + 3*64*XS*2 + ro, &g_VTlo[vbase  + (size_t)r*S_ + n0 + c8*8]);
        }
        CP_COMMIT();
    };

    issue(0, 0);

    for (int tile = 0; tile < S_/64; tile++) {
        if (tile + 1 < S_/64) {
            issue((tile+1)*64, (tile+1) & 1);
            CP_WAIT(1);
        } else {
            CP_WAIT(0);
        }
        __syncthreads();

        bf16* Khs = smA + (tile & 1) * STG_ELEMS;
        bf16* Kls = Khs + 64*XS;
        bf16* Vhs = Khs + 2*64*XS;
        bf16* Vls = Khs + 3*64*XS;

        // ---- S = Q K^T ----
        float s[8][4];
#pragma unroll
        for (int nb = 0; nb < 8; nb++)
#pragma unroll
            for (int j = 0; j < 4; j++) s[nb][j] = 0.0f;

#pragma unroll
        for (int ks = 0; ks < 4; ks++) {
#pragma unroll
            for (int nb = 0; nb < 8; nb++) {
                uint32_t kb0 = ld32(&Khs[(nb*8+g)*XS + ks*16 + 2*q]);
                uint32_t kb1 = ld32(&Khs[(nb*8+g)*XS + ks*16 + 8 + 2*q]);
                uint32_t kl0 = ld32(&Kls[(nb*8+g)*XS + ks*16 + 2*q]);
                uint32_t kl1 = ld32(&Kls[(nb*8+g)*XS + ks*16 + 8 + 2*q]);
                mma4(s[nb], qh[ks], kb0, kb1);
                mma4(s[nb], qh[ks], kl0, kl1);
                mma4(s[nb], ql[ks], kb0, kb1);
            }
        }

        // ---- online softmax ----
        float tm1 = -1e30f, tm2 = -1e30f;
#pragma unroll
        for (int nb = 0; nb < 8; nb++) {
            tm1 = fmaxf(tm1, fmaxf(s[nb][0], s[nb][1]));
            tm2 = fmaxf(tm2, fmaxf(s[nb][2], s[nb][3]));
        }
        tm1 = fmaxf(tm1, __shfl_xor_sync(0xffffffffu, tm1, 1));
        tm1 = fmaxf(tm1, __shfl_xor_sync(0xffffffffu, tm1, 2));
        tm2 = fmaxf(tm2, __shfl_xor_sync(0xffffffffu, tm2, 1));
        tm2 = fmaxf(tm2, __shfl_xor_sync(0xffffffffu, tm2, 2));

        float mn1 = fmaxf(m1, tm1), mn2 = fmaxf(m2, tm2);
        float c1f = __expf(m1 - mn1), c2f = __expf(m2 - mn2);

        float sum1 = 0.0f, sum2 = 0.0f;
#pragma unroll
        for (int nb = 0; nb < 8; nb++) {
            s[nb][0] = __expf(s[nb][0] - mn1);
            s[nb][1] = __expf(s[nb][1] - mn1);
            s[nb][2] = __expf(s[nb][2] - mn2);
            s[nb][3] = __expf(s[nb][3] - mn2);
            sum1 += s[nb][0] + s[nb][1];
            sum2 += s[nb][2] + s[nb][3];
        }
        sum1 += __shfl_xor_sync(0xffffffffu, sum1, 1);
        sum1 += __shfl_xor_sync(0xffffffffu, sum1, 2);
        sum2 += __shfl_xor_sync(0xffffffffu, sum2, 1);
        sum2 += __shfl_xor_sync(0xffffffffu, sum2, 2);

        l1 = l1 * c1f + sum1;  m1 = mn1;
        l2 = l2 * c2f + sum2;  m2 = mn2;
#pragma unroll
        for (int nb = 0; nb < 8; nb++) {
            o[nb][0] *= c1f; o[nb][1] *= c1f;
            o[nb][2] *= c2f; o[nb][3] *= c2f;
        }

        // ---- ctx += P V ----
#pragma unroll
        for (int j = 0; j < 4; j++) {
            uint32_t pa_h[4], pa_l[4];
            split_pack(s[2*j  ][0], s[2*j  ][1], pa_h[0], pa_l[0]);
            split_pack(s[2*j  ][2], s[2*j  ][3], pa_h[1], pa_l[1]);
            split_pack(s[2*j+1][0], s[2*j+1][1], pa_h[2], pa_l[2]);
            split_pack(s[2*j+1][2], s[2*j+1][3], pa_h[3], pa_l[3]);
#pragma unroll
            for (int nb = 0; nb < 8; nb++) {
                uint32_t vh0 = ld32(&Vhs[(nb*8+g)*XS + j*16 + 2*q]);
                uint32_t vh1 = ld32(&Vhs[(nb*8+g)*XS + j*16 + 8 + 2*q]);
                uint32_t vl0 = ld32(&Vls[(nb*8+g)*XS + j*16 + 2*q]);
                uint32_t vl1 = ld32(&Vls[(nb*8+g)*XS + j*16 + 8 + 2*q]);
                mma4(o[nb], pa_h, vh0, vh1);
                mma4(o[nb], pa_h, vl0, vl1);
                mma4(o[nb], pa_l, vh0, vh1);
            }
        }
        __syncthreads();   // stage reads done before reuse at tile+2
    }

    // ---- epilogue ----
    float inv1 = 1.0f / l1, inv2 = 1.0f / l2;
    int b = bh / H_, h = bh % H_;
#pragma unroll
    for (int nb = 0; nb < 8; nb++) {
        int col = h*HD_ + nb*8 + 2*q;
        float v00 = o[nb][0]*inv1, v01 = o[nb][1]*inv1;
        float v10 = o[nb][2]*inv2, v11 = o[nb][3]*inv2;
        size_t r1 = ((size_t)b*S_ + m0 + lr    ) * D_ + col;
        size_t r2 = ((size_t)b*S_ + m0 + lr + 8) * D_ + col;
        bf16 h0,l0,h1,l1b;
        splitf(v00,h0,l0); splitf(v01,h1,l1b);
        __nv_bfloat162 ph; ph.x=h0; ph.y=h1;
        __nv_bfloat162 pl; pl.x=l0; pl.y=l1b;
        *reinterpret_cast<__nv_bfloat162*>(&g_chi[r1]) = ph;
        *reinterpret_cast<__nv_bfloat162*>(&g_clo[r1]) = pl;
        splitf(v10,h0,l0); splitf(v11,h1,l1b);
        ph.x=h0; ph.y=h1; pl.x=l0; pl.y=l1b;
        *reinterpret_cast<__nv_bfloat162*>(&g_chi[r2]) = ph;
        *reinterpret_cast<__nv_bfloat162*>(&g_clo[r2]) = pl;
    }
}

// --------------------------- output projection -------------------------------
__global__ void __launch_bounds__(256, 2)
proj_kernel(const float* __restrict__ bp, float* __restrict__ out) {
    extern __shared__ bf16 dsm[];
    bf16* xs_h = dsm;
    bf16* xs_l = dsm + 128*XS;
    bf16* ws_h = dsm + 2*128*XS;
    bf16* ws_l = dsm + 2*128*XS + 64*XS;

    const int n0 = blockIdx.x * 64;
    const int m0 = blockIdx.y * 128;
    const int t = threadIdx.x, w = t >> 5, lane = t & 31;
    const int g = lane >> 2, q = lane & 3;

    float acc[8][4];
#pragma unroll
    for (int nb = 0; nb < 8; nb++)
#pragma unroll
        for (int j = 0; j < 4; j++) acc[nb][j] = 0.0f;

    for (int kc = 0; kc < D_; kc += 64) {
        __syncthreads();
#pragma unroll
        for (int ii = 0; ii < 4; ii++) {              // 1024 uint4
            int i = t + ii*256;
            int r = i >> 3, c8 = i & 7;
            *reinterpret_cast<uint4*>(&xs_h[r*XS + c8*8]) =
                *reinterpret_cast<const uint4*>(&g_chi[(size_t)(m0+r)*D_ + kc + c8*8]);
            *reinterpret_cast<uint4*>(&xs_l[r*XS + c8*8]) =
                *reinterpret_cast<const uint4*>(&g_clo[(size_t)(m0+r)*D_ + kc + c8*8]);
        }
        {
            int r = t >> 2, c8 = (t & 3) * 2;
#pragma unroll
            for (int jj = 0; jj < 2; jj++) {
                *reinterpret_cast<uint4*>(&ws_h[r*XS + (c8+jj)*8]) =
                    *reinterpret_cast<const uint4*>(&g_WpThi[(size_t)(n0+r)*D_ + kc + (c8+jj)*8]);
                *reinterpret_cast<uint4*>(&ws_l[r*XS + (c8+jj)*8]) =
                    *reinterpret_cast<const uint4*>(&g_WpTlo[(size_t)(n0+r)*D_ + kc + (c8+jj)*8]);
            }
        }
        __syncthreads();

#pragma unroll
        for (int ks = 0; ks < 4; ks++) {
            const int ar = w*16 + g;
            uint32_t ah[4], al[4];
            ah[0] = ld32(&xs_h[(ar  )*XS + ks*16 + 2*q]);
            ah[1] = ld32(&xs_h[(ar+8)*XS + ks*16 + 2*q]);
            ah[2] = ld32(&xs_h[(ar  )*XS + ks*16 + 8 + 2*q]);
            ah[3] = ld32(&xs_h[(ar+8)*XS + ks*16 + 8 + 2*q]);
            al[0] = ld32(&xs_l[(ar  )*XS + ks*16 + 2*q]);
            al[1] = ld32(&xs_l[(ar+8)*XS + ks*16 + 2*q]);
            al[2] = ld32(&xs_l[(ar  )*XS + ks*16 + 8 + 2*q]);
            al[3] = ld32(&xs_l[(ar+8)*XS + ks*16 + 8 + 2*q]);
#pragma unroll
            for (int nb = 0; nb < 8; nb++) {
                uint32_t bh0 = ld32(&ws_h[(nb*8+g)*XS + ks*16 + 2*q]);
                uint32_t bh1 = ld32(&ws_h[(nb*8+g)*XS + ks*16 + 8 + 2*q]);
                uint32_t bl0 = ld32(&ws_l[(nb*8+g)*XS + ks*16 + 2*q]);
                uint32_t bl1 = ld32(&ws_l[(nb*8+g)*XS + ks*16 + 8 + 2*q]);
                mma4(acc[nb], ah, bh0, bh1);
                mma4(acc[nb], ah, bl0, bl1);
                mma4(acc[nb], al, bh0, bh1);
            }
        }
    }

    const int lr = w*16 + g;
#pragma unroll
    for (int nb = 0; nb < 8; nb++) {
        int col = n0 + nb*8 + 2*q;
        float b0 = bp[col], b1 = bp[col+1];
        float2 v0 = make_float2(acc[nb][0] + b0, acc[nb][1] + b1);
        float2 v1 = make_float2(acc[nb][2] + b0, acc[nb][3] + b1);
        *reinterpret_cast<float2*>(&out[(size_t)(m0 + lr    )*D_ + col]) = v0;
        *reinterpret_cast<float2*>(&out[(size_t)(m0 + lr + 8)*D_ + col]) = v1;
    }
}

// -----------------------------------------------------------------------------
extern "C" void kernel_launch(void* const* d_in, const int* in_sizes, int n_in,
                              void* d_out, int out_size)
{
    const float* x  = (const float*)d_in[0];
    const float* Wq = (const float*)d_in[1];
    const float* bq = (const float*)d_in[2];
    const float* Wk = (const float*)d_in[3];
    const float* bk = (const float*)d_in[4];
    const float* Wv = (const float*)d_in[5];
    const float* bv = (const float*)d_in[6];
    const float* Wp = (const float*)d_in[7];
    const float* bp = (const float*)d_in[8];
    float* out = (float*)d_out;

    cudaFuncSetAttribute(qkv_kernel,  cudaFuncAttributeMaxDynamicSharedMemorySize, QKV_SMEM);
    cudaFuncSetAttribute(proj_kernel, cudaFuncAttributeMaxDynamicSharedMemorySize, QKV_SMEM);
    cudaFuncSetAttribute(attn_kernel, cudaFuncAttributeMaxDynamicSharedMemorySize, ATTN_DSMEM);

    prep_x<<<(B_*S_*D_/4 + 255)/256, 256>>>(x);
    prep_w<<<(3*H_*D_*HD_ + 255)/256, 256>>>(Wq, Wk, Wv, Wp);

    qkv_kernel<<<dim3(3*H_, S_/128, B_), 256, QKV_SMEM>>>(bq, bk, bv);
    attn_kernel<<<dim3(S_/128, BH_), 256, ATTN_DSMEM>>>();
    proj_kernel<<<dim3(D_/64, (B_*S_)/128), 256, QKV_SMEM>>>(bp, out);
}

// round 16
// speedup vs baseline: 4.9913x; 1.0703x over previous
#include <cuda_runtime.h>
#include <cuda_bf16.h>
#include <stdint.h>

#define B_  8
#define S_  2048
#define D_  768
#define H_  12
#define HD_ 64
#define BH_ (B_*H_)

typedef __nv_bfloat16 bf16;

// ------------------------- global scratch (no allocs) -----------------------
__device__ __align__(16) bf16 g_xhi [(size_t)B_*S_*D_];
__device__ __align__(16) bf16 g_xlo [(size_t)B_*S_*D_];
__device__ __align__(16) bf16 g_WThi[(size_t)3*H_*HD_*D_];   // [type][h][e_out][d_in]
__device__ __align__(16) bf16 g_WTlo[(size_t)3*H_*HD_*D_];
__device__ __align__(16) bf16 g_WpThi[(size_t)D_*D_];        // [e_out][d_in]
__device__ __align__(16) bf16 g_WpTlo[(size_t)D_*D_];
__device__ __align__(16) bf16 g_Qhi [(size_t)BH_*S_*HD_];
__device__ __align__(16) bf16 g_Qlo [(size_t)BH_*S_*HD_];
__device__ __align__(16) bf16 g_Khi [(size_t)BH_*S_*HD_];
__device__ __align__(16) bf16 g_Klo [(size_t)BH_*S_*HD_];
__device__ __align__(16) bf16 g_VThi[(size_t)BH_*HD_*S_];    // [bh][e][s]
__device__ __align__(16) bf16 g_VTlo[(size_t)BH_*HD_*S_];
__device__ __align__(16) bf16 g_chi [(size_t)B_*S_*D_];
__device__ __align__(16) bf16 g_clo [(size_t)B_*S_*D_];

// ------------------------------- helpers ------------------------------------
__device__ __forceinline__ void splitf(float x, bf16& h, bf16& l) {
    h = __float2bfloat16(x);
    l = __float2bfloat16(x - __bfloat162float(h));
}

__device__ __forceinline__ void split_pack(float a, float b, uint32_t& hi, uint32_t& lo) {
    bf16 ah, al, bh2, bl;
    splitf(a, ah, al);
    splitf(b, bh2, bl);
    __nv_bfloat162 Hh; Hh.x = ah; Hh.y = bh2;
    __nv_bfloat162 Ll; Ll.x = al; Ll.y = bl;
    hi = *reinterpret_cast<uint32_t*>(&Hh);
    lo = *reinterpret_cast<uint32_t*>(&Ll);
}

__device__ __forceinline__ uint32_t smem_u32(const void* p) {
    uint32_t a;
    asm("{ .reg .u64 t; cvta.to.shared.u64 t, %1; cvt.u32.u64 %0, t; }"
        : "=r"(a) : "l"(p));
    return a;
}

__device__ __forceinline__ void cpa16(uint32_t dst, const void* src) {
    asm volatile("cp.async.cg.shared.global [%0], [%1], 16;"
                 :: "r"(dst), "l"(src) : "memory");
}
#define CP_COMMIT() asm volatile("cp.async.commit_group;" ::: "memory")
#define CP_WAIT(n)  asm volatile("cp.async.wait_group %0;" :: "n"(n) : "memory")

// ldmatrix x4: four 8x8 b16 fragments in one instruction (sm_75+)
__device__ __forceinline__ void ldm4(uint32_t* r, uint32_t a) {
    asm volatile("ldmatrix.sync.aligned.m8n8.x4.shared.b16 {%0,%1,%2,%3}, [%4];"
        : "=r"(r[0]), "=r"(r[1]), "=r"(r[2]), "=r"(r[3]) : "r"(a));
}

// D += A * B  (m16n8k16, bf16 in, f32 acc)
__device__ __forceinline__ void mma4(float* c, const uint32_t* a, uint32_t b0, uint32_t b1) {
    asm volatile(
        "mma.sync.aligned.m16n8k16.row.col.f32.bf16.bf16.f32 "
        "{%0,%1,%2,%3}, {%4,%5,%6,%7}, {%8,%9}, {%0,%1,%2,%3};\n"
        : "+f"(c[0]), "+f"(c[1]), "+f"(c[2]), "+f"(c[3])
        : "r"(a[0]), "r"(a[1]), "r"(a[2]), "r"(a[3]), "r"(b0), "r"(b1));
}

// ------------------------------- prep ---------------------------------------
__global__ void __launch_bounds__(256)
prep_x(const float* __restrict__ x) {
    size_t i4 = (size_t)blockIdx.x * blockDim.x + threadIdx.x;
    if (i4 >= (size_t)B_*S_*D_/4) return;
    float4 v = reinterpret_cast<const float4*>(x)[i4];
    bf16 h0,l0,h1,l1,h2,l2,h3,l3;
    splitf(v.x,h0,l0); splitf(v.y,h1,l1); splitf(v.z,h2,l2); splitf(v.w,h3,l3);
    __nv_bfloat162* dh = reinterpret_cast<__nv_bfloat162*>(g_xhi);
    __nv_bfloat162* dl = reinterpret_cast<__nv_bfloat162*>(g_xlo);
    __nv_bfloat162 a; a.x=h0; a.y=h1; dh[i4*2]   = a;
    a.x=h2; a.y=h3;             dh[i4*2+1] = a;
    a.x=l0; a.y=l1;             dl[i4*2]   = a;
    a.x=l2; a.y=l3;             dl[i4*2+1] = a;
}

__global__ void __launch_bounds__(256)
prep_w(const float* __restrict__ Wq, const float* __restrict__ Wk,
       const float* __restrict__ Wv, const float* __restrict__ Wp) {
    int idx = blockIdx.x * blockDim.x + threadIdx.x;
    const int NW = 3*H_*D_*HD_;
    if (idx < NW) {
        int type = idx / (H_*D_*HD_);
        int rem  = idx % (H_*D_*HD_);
        int h    = rem / (D_*HD_);
        int rem2 = rem % (D_*HD_);
        int d    = rem2 / HD_;
        int e    = rem2 % HD_;
        const float* W = (type==0) ? Wq : (type==1) ? Wk : Wv;
        float v = W[((size_t)h*D_ + d)*HD_ + e];
        bf16 hi, lo; splitf(v, hi, lo);
        size_t dst = ((size_t)(type*H_ + h)*HD_ + e)*D_ + d;
        g_WThi[dst] = hi; g_WTlo[dst] = lo;
    }
    if (idx < D_*D_) {
        int d = idx / D_, e = idx % D_;
        float v = Wp[idx];
        bf16 hi, lo; splitf(v, hi, lo);
        g_WpThi[(size_t)e*D_ + d] = hi;
        g_WpTlo[(size_t)e*D_ + d] = lo;
    }
}

// --------------------- shared GEMM mainloop (ldmatrix) -----------------------
#define XS 72
#define VTS 136
#define QKV_SMEM ((128*XS*2 + 64*XS*2) * 2)   // bytes (bf16)

// A-fragment lane offset (bytes): row=(bit3?8:0)+lane&7, col=(bit4?8:0)
#define AFO(lane) (((((lane)>>3)&1)*8 + ((lane)&7))*(XS*2) + (((lane)>>4)&1)*16)
// B-fragment, nb-pair covering: row=(bit4?8:0)+lane&7, col=(bit3?8:0)
#define BFO2(lane) (((((lane)>>4)&1)*8 + ((lane)&7))*(XS*2) + (((lane)>>3)&1)*16)
// B-fragment, ks-pair covering: row=lane&7, col=ks-half(bit4)*16 + (bit3?8:0)
#define BFOK(lane) (((lane)&7)*(XS*2) + (((lane)>>4)&1)*32 + (((lane)>>3)&1)*16)

__device__ __forceinline__ void gemm_chunk(
    const bf16* xs_h, const bf16* xs_l,
    const bf16* ws_h, const bf16* ws_l,
    float acc[8][4], int w, int lane)
{
    const uint32_t xh = smem_u32(xs_h) + w*16*(XS*2) + AFO(lane);
    const uint32_t xl = smem_u32(xs_l) + w*16*(XS*2) + AFO(lane);
    const uint32_t wh = smem_u32(ws_h) + BFO2(lane);
    const uint32_t wl = smem_u32(ws_l) + BFO2(lane);

#pragma unroll
    for (int ks = 0; ks < 4; ks++) {
        uint32_t ah[4], al[4];
        ldm4(ah, xh + ks*32);
        ldm4(al, xl + ks*32);
#pragma unroll
        for (int nbp = 0; nbp < 4; nbp++) {
            uint32_t bf[4];
            ldm4(bf, wh + nbp*(16*XS*2) + ks*32);
            mma4(acc[2*nbp  ], ah, bf[0], bf[1]);
            mma4(acc[2*nbp+1], ah, bf[2], bf[3]);
            mma4(acc[2*nbp  ], al, bf[0], bf[1]);
            mma4(acc[2*nbp+1], al, bf[2], bf[3]);
            ldm4(bf, wl + nbp*(16*XS*2) + ks*32);
            mma4(acc[2*nbp  ], ah, bf[0], bf[1]);
            mma4(acc[2*nbp+1], ah, bf[2], bf[3]);
        }
    }
}

// ------------------------ QKV projection (mma) -------------------------------
__global__ void __launch_bounds__(256, 2)
qkv_kernel(const float* __restrict__ bq, const float* __restrict__ bk,
           const float* __restrict__ bv) {
    extern __shared__ bf16 dsm[];
    bf16* xs_h = dsm;                 // 128*72
    bf16* xs_l = dsm + 128*XS;
    bf16* ws_h = dsm + 2*128*XS;      // 64*72
    bf16* ws_l = dsm + 2*128*XS + 64*XS;

    const int type = blockIdx.x / H_;
    const int h    = blockIdx.x % H_;
    const int m0   = blockIdx.y * 128;
    const int b    = blockIdx.z;
    const int bh   = b*H_ + h;

    const int t = threadIdx.x, w = t >> 5, lane = t & 31;
    const int g = lane >> 2, q = lane & 3;

    const size_t xbase = (size_t)(b*S_ + m0) * D_;
    const size_t wbase = (size_t)(type*H_ + h) * HD_ * D_;

    float acc[8][4];
#pragma unroll
    for (int nb = 0; nb < 8; nb++)
#pragma unroll
        for (int j = 0; j < 4; j++) acc[nb][j] = 0.0f;

    for (int kc = 0; kc < D_; kc += 64) {
        __syncthreads();
#pragma unroll
        for (int ii = 0; ii < 4; ii++) {               // x tile: 1024 uint4
            int i = t + ii*256;
            int r = i >> 3, c8 = i & 7;
            *reinterpret_cast<uint4*>(&xs_h[r*XS + c8*8]) =
                *reinterpret_cast<const uint4*>(&g_xhi[xbase + (size_t)r*D_ + kc + c8*8]);
            *reinterpret_cast<uint4*>(&xs_l[r*XS + c8*8]) =
                *reinterpret_cast<const uint4*>(&g_xlo[xbase + (size_t)r*D_ + kc + c8*8]);
        }
        {                                              // W tile: 256 uint4
            int r = t >> 2, c8 = (t & 3) * 2;
#pragma unroll
            for (int jj = 0; jj < 2; jj++) {
                *reinterpret_cast<uint4*>(&ws_h[r*XS + (c8+jj)*8]) =
                    *reinterpret_cast<const uint4*>(&g_WThi[wbase + (size_t)r*D_ + kc + (c8+jj)*8]);
                *reinterpret_cast<uint4*>(&ws_l[r*XS + (c8+jj)*8]) =
                    *reinterpret_cast<const uint4*>(&g_WTlo[wbase + (size_t)r*D_ + kc + (c8+jj)*8]);
            }
        }
        __syncthreads();
        gemm_chunk(xs_h, xs_l, ws_h, ws_l, acc, w, lane);
    }

    const float* bias = (type==0) ? bq : (type==1) ? bk : bv;
    const float rscale = 1.0f / (8.0f + 1e-6f);
    const int lr = w*16 + g;
#pragma unroll
    for (int nb = 0; nb < 8; nb++) {
        int col = nb*8 + 2*q;
        float b0 = bias[h*HD_ + col], b1 = bias[h*HD_ + col + 1];
        acc[nb][0] += b0; acc[nb][1] += b1;
        acc[nb][2] += b0; acc[nb][3] += b1;
        if (type == 0) {
            acc[nb][0] *= rscale; acc[nb][1] *= rscale;
            acc[nb][2] *= rscale; acc[nb][3] *= rscale;
        }
    }

    if (type < 2) {
        bf16* dh = (type==0) ? g_Qhi : g_Khi;
        bf16* dl = (type==0) ? g_Qlo : g_Klo;
        size_t obase = (size_t)bh * S_ * HD_;
#pragma unroll
        for (int nb = 0; nb < 8; nb++) {
            int col = nb*8 + 2*q;
#pragma unroll
            for (int rr = 0; rr < 2; rr++) {
                int grow = m0 + lr + rr*8;
                bf16 h0,l0,h1,l1;
                splitf(acc[nb][rr*2+0], h0, l0);
                splitf(acc[nb][rr*2+1], h1, l1);
                __nv_bfloat162 ph; ph.x=h0; ph.y=h1;
                __nv_bfloat162 pl; pl.x=l0; pl.y=l1;
                *reinterpret_cast<__nv_bfloat162*>(&dh[obase + (size_t)grow*HD_ + col]) = ph;
                *reinterpret_cast<__nv_bfloat162*>(&dl[obase + (size_t)grow*HD_ + col]) = pl;
            }
        }
    } else {
        bf16* vt = dsm;                       // 64 x 136
        size_t obase = (size_t)bh * HD_ * S_;
#pragma unroll
        for (int p = 0; p < 2; p++) {
            __syncthreads();
#pragma unroll
            for (int nb = 0; nb < 8; nb++) {
                int col = nb*8 + 2*q;
#pragma unroll
                for (int rr = 0; rr < 2; rr++) {
                    int r = lr + rr*8;
                    bf16 h0,l0,h1,l1;
                    splitf(acc[nb][rr*2+0], h0, l0);
                    splitf(acc[nb][rr*2+1], h1, l1);
                    vt[(col  )*VTS + r] = p ? l0 : h0;
                    vt[(col+1)*VTS + r] = p ? l1 : h1;
                }
            }
            __syncthreads();
            bf16* dst = p ? g_VTlo : g_VThi;
#pragma unroll
            for (int ii = 0; ii < 4; ii++) {          // 1024 uint4
                int i = t + ii*256;
                int col = i >> 4, r8 = i & 15;
                *reinterpret_cast<uint4*>(&dst[obase + (size_t)col*S_ + m0 + r8*8]) =
                    *reinterpret_cast<uint4*>(&vt[col*VTS + r8*8]);
            }
        }
    }
}

// ------------------ flash attention (mma.sync + cp.async + ldmatrix) ---------
#define STG_ELEMS (4*64*XS)                 // bf16 elems per stage
#define ATTN_DSMEM (2*STG_ELEMS*2)

__global__ void __launch_bounds__(256, 2)
attn_kernel() {
    extern __shared__ bf16 smA[];
    const uint32_t smb = smem_u32(smA);

    const int bh = blockIdx.y;
    const int m0 = blockIdx.x * 128;
    const int t = threadIdx.x, w = t >> 5, lane = t & 31;
    const int g = lane >> 2, q = lane & 3;
    const int lr = w*16 + g;

    const size_t qkbase = (size_t)bh * S_ * HD_;
    const size_t vbase  = (size_t)bh * HD_ * S_;

    // Q fragments in registers
    uint32_t qh[4][4], ql[4][4];
#pragma unroll
    for (int ks = 0; ks < 4; ks++) {
        const bf16* qhp = &g_Qhi[qkbase + (size_t)(m0+lr)*HD_ + ks*16 + 2*q];
        const bf16* qlp = &g_Qlo[qkbase + (size_t)(m0+lr)*HD_ + ks*16 + 2*q];
        qh[ks][0] = *reinterpret_cast<const uint32_t*>(qhp);
        qh[ks][1] = *reinterpret_cast<const uint32_t*>(qhp + 8*HD_);
        qh[ks][2] = *reinterpret_cast<const uint32_t*>(qhp + 8);
        qh[ks][3] = *reinterpret_cast<const uint32_t*>(qhp + 8*HD_ + 8);
        ql[ks][0] = *reinterpret_cast<const uint32_t*>(qlp);
        ql[ks][1] = *reinterpret_cast<const uint32_t*>(qlp + 8*HD_);
        ql[ks][2] = *reinterpret_cast<const uint32_t*>(qlp + 8);
        ql[ks][3] = *reinterpret_cast<const uint32_t*>(qlp + 8*HD_ + 8);
    }

    float m1 = -1e30f, m2 = -1e30f, l1 = 0.0f, l2 = 0.0f;
    float o[8][4];
#pragma unroll
    for (int nb = 0; nb < 8; nb++)
#pragma unroll
        for (int j = 0; j < 4; j++) o[nb][j] = 0.0f;

    auto issue = [&](int n0, int st) {
        uint32_t sb = smb + (uint32_t)st * STG_ELEMS * 2;
#pragma unroll
        for (int ii = 0; ii < 2; ii++) {
            int i = t + ii*256;
            int r = i >> 3, c8 = i & 7;
            uint32_t ro = (uint32_t)(r*XS + c8*8) * 2;
            cpa16(sb + 0*64*XS*2 + ro, &g_Khi [qkbase + (size_t)(n0+r)*HD_ + c8*8]);
            cpa16(sb + 1*64*XS*2 + ro, &g_Klo [qkbase + (size_t)(n0+r)*HD_ + c8*8]);
            cpa16(sb + 2*64*XS*2 + ro, &g_VThi[vbase  + (size_t)r*S_ + n0 + c8*8]);
            cpa16(sb + 3*64*XS*2 + ro, &g_VTlo[vbase  + (size_t)r*S_ + n0 + c8*8]);
        }
        CP_COMMIT();
    };

    issue(0, 0);

    const uint32_t bfok = BFOK(lane);
    const uint32_t bfo2 = BFO2(lane);

    for (int tile = 0; tile < S_/64; tile++) {
        if (tile + 1 < S_/64) {
            issue((tile+1)*64, (tile+1) & 1);
            CP_WAIT(1);
        } else {
            CP_WAIT(0);
        }
        __syncthreads();

        const uint32_t st_u32 = smb + (uint32_t)(tile & 1) * STG_ELEMS * 2;
        const uint32_t kh_u32 = st_u32;
        const uint32_t kl_u32 = st_u32 + 1*64*XS*2;
        const uint32_t vh_u32 = st_u32 + 2*64*XS*2;
        const uint32_t vl_u32 = st_u32 + 3*64*XS*2;

        // ---- S = Q K^T (ldmatrix fragments) ----
        float s[8][4];
#pragma unroll
        for (int nb = 0; nb < 8; nb++)
#pragma unroll
            for (int j = 0; j < 4; j++) s[nb][j] = 0.0f;

#pragma unroll
        for (int nb = 0; nb < 8; nb++) {
            uint32_t kf[8];
            uint32_t base = kh_u32 + nb*(8*XS*2) + bfok;
            ldm4(kf + 0, base);
            ldm4(kf + 4, base + 64);
#pragma unroll
            for (int ks = 0; ks < 4; ks++) {
                mma4(s[nb], qh[ks], kf[2*ks], kf[2*ks+1]);
                mma4(s[nb], ql[ks], kf[2*ks], kf[2*ks+1]);
            }
            base = kl_u32 + nb*(8*XS*2) + bfok;
            ldm4(kf + 0, base);
            ldm4(kf + 4, base + 64);
#pragma unroll
            for (int ks = 0; ks < 4; ks++)
                mma4(s[nb], qh[ks], kf[2*ks], kf[2*ks+1]);
        }

        // ---- online softmax ----
        float tm1 = -1e30f, tm2 = -1e30f;
#pragma unroll
        for (int nb = 0; nb < 8; nb++) {
            tm1 = fmaxf(tm1, fmaxf(s[nb][0], s[nb][1]));
            tm2 = fmaxf(tm2, fmaxf(s[nb][2], s[nb][3]));
        }
        tm1 = fmaxf(tm1, __shfl_xor_sync(0xffffffffu, tm1, 1));
        tm1 = fmaxf(tm1, __shfl_xor_sync(0xffffffffu, tm1, 2));
        tm2 = fmaxf(tm2, __shfl_xor_sync(0xffffffffu, tm2, 1));
        tm2 = fmaxf(tm2, __shfl_xor_sync(0xffffffffu, tm2, 2));

        float mn1 = fmaxf(m1, tm1), mn2 = fmaxf(m2, tm2);
        float c1f = __expf(m1 - mn1), c2f = __expf(m2 - mn2);

        float sum1 = 0.0f, sum2 = 0.0f;
#pragma unroll
        for (int nb = 0; nb < 8; nb++) {
            s[nb][0] = __expf(s[nb][0] - mn1);
            s[nb][1] = __expf(s[nb][1] - mn1);
            s[nb][2] = __expf(s[nb][2] - mn2);
            s[nb][3] = __expf(s[nb][3] - mn2);
            sum1 += s[nb][0] + s[nb][1];
            sum2 += s[nb][2] + s[nb][3];
        }
        sum1 += __shfl_xor_sync(0xffffffffu, sum1, 1);
        sum1 += __shfl_xor_sync(0xffffffffu, sum1, 2);
        sum2 += __shfl_xor_sync(0xffffffffu, sum2, 1);
        sum2 += __shfl_xor_sync(0xffffffffu, sum2, 2);

        l1 = l1 * c1f + sum1;  m1 = mn1;
        l2 = l2 * c2f + sum2;  m2 = mn2;
#pragma unroll
        for (int nb = 0; nb < 8; nb++) {
            o[nb][0] *= c1f; o[nb][1] *= c1f;
            o[nb][2] *= c2f; o[nb][3] *= c2f;
        }

        // ---- ctx += P V (ldmatrix V fragments, nb-pair covering) ----
#pragma unroll
        for (int j = 0; j < 4; j++) {
            uint32_t pa_h[4], pa_l[4];
            split_pack(s[2*j  ][0], s[2*j  ][1], pa_h[0], pa_l[0]);
            split_pack(s[2*j  ][2], s[2*j  ][3], pa_h[1], pa_l[1]);
            split_pack(s[2*j+1][0], s[2*j+1][1], pa_h[2], pa_l[2]);
            split_pack(s[2*j+1][2], s[2*j+1][3], pa_h[3], pa_l[3]);
#pragma unroll
            for (int nbp = 0; nbp < 4; nbp++) {
                uint32_t vf[4];
                ldm4(vf, vh_u32 + nbp*(16*XS*2) + bfo2 + j*32);
                mma4(o[2*nbp  ], pa_h, vf[0], vf[1]);
                mma4(o[2*nbp+1], pa_h, vf[2], vf[3]);
                mma4(o[2*nbp  ], pa_l, vf[0], vf[1]);
                mma4(o[2*nbp+1], pa_l, vf[2], vf[3]);
                ldm4(vf, vl_u32 + nbp*(16*XS*2) + bfo2 + j*32);
                mma4(o[2*nbp  ], pa_h, vf[0], vf[1]);
                mma4(o[2*nbp+1], pa_h, vf[2], vf[3]);
            }
        }
        __syncthreads();   // stage reads done before reuse at tile+2
    }

    // ---- epilogue ----
    float inv1 = 1.0f / l1, inv2 = 1.0f / l2;
    int b = bh / H_, h = bh % H_;
#pragma unroll
    for (int nb = 0; nb < 8; nb++) {
        int col = h*HD_ + nb*8 + 2*q;
        float v00 = o[nb][0]*inv1, v01 = o[nb][1]*inv1;
        float v10 = o[nb][2]*inv2, v11 = o[nb][3]*inv2;
        size_t r1 = ((size_t)b*S_ + m0 + lr    ) * D_ + col;
        size_t r2 = ((size_t)b*S_ + m0 + lr + 8) * D_ + col;
        bf16 h0,l0,h1,l1b;
        splitf(v00,h0,l0); splitf(v01,h1,l1b);
        __nv_bfloat162 ph; ph.x=h0; ph.y=h1;
        __nv_bfloat162 pl; pl.x=l0; pl.y=l1b;
        *reinterpret_cast<__nv_bfloat162*>(&g_chi[r1]) = ph;
        *reinterpret_cast<__nv_bfloat162*>(&g_clo[r1]) = pl;
        splitf(v10,h0,l0); splitf(v11,h1,l1b);
        ph.x=h0; ph.y=h1; pl.x=l0; pl.y=l1b;
        *reinterpret_cast<__nv_bfloat162*>(&g_chi[r2]) = ph;
        *reinterpret_cast<__nv_bfloat162*>(&g_clo[r2]) = pl;
    }
}

// --------------------------- output projection -------------------------------
__global__ void __launch_bounds__(256, 2)
proj_kernel(const float* __restrict__ bp, float* __restrict__ out) {
    extern __shared__ bf16 dsm[];
    bf16* xs_h = dsm;
    bf16* xs_l = dsm + 128*XS;
    bf16* ws_h = dsm + 2*128*XS;
    bf16* ws_l = dsm + 2*128*XS + 64*XS;

    const int n0 = blockIdx.x * 64;
    const int m0 = blockIdx.y * 128;
    const int t = threadIdx.x, w = t >> 5, lane = t & 31;
    const int g = lane >> 2, q = lane & 3;

    float acc[8][4];
#pragma unroll
    for (int nb = 0; nb < 8; nb++)
#pragma unroll
        for (int j = 0; j < 4; j++) acc[nb][j] = 0.0f;

    for (int kc = 0; kc < D_; kc += 64) {
        __syncthreads();
#pragma unroll
        for (int ii = 0; ii < 4; ii++) {              // 1024 uint4
            int i = t + ii*256;
            int r = i >> 3, c8 = i & 7;
            *reinterpret_cast<uint4*>(&xs_h[r*XS + c8*8]) =
                *reinterpret_cast<const uint4*>(&g_chi[(size_t)(m0+r)*D_ + kc + c8*8]);
            *reinterpret_cast<uint4*>(&xs_l[r*XS + c8*8]) =
                *reinterpret_cast<const uint4*>(&g_clo[(size_t)(m0+r)*D_ + kc + c8*8]);
        }
        {
            int r = t >> 2, c8 = (t & 3) * 2;
#pragma unroll
            for (int jj = 0; jj < 2; jj++) {
                *reinterpret_cast<uint4*>(&ws_h[r*XS + (c8+jj)*8]) =
                    *reinterpret_cast<const uint4*>(&g_WpThi[(size_t)(n0+r)*D_ + kc + (c8+jj)*8]);
                *reinterpret_cast<uint4*>(&ws_l[r*XS + (c8+jj)*8]) =
                    *reinterpret_cast<const uint4*>(&g_WpTlo[(size_t)(n0+r)*D_ + kc + (c8+jj)*8]);
            }
        }
        __syncthreads();
        gemm_chunk(xs_h, xs_l, ws_h, ws_l, acc, w, lane);
    }

    const int lr = w*16 + g;
#pragma unroll
    for (int nb = 0; nb < 8; nb++) {
        int col = n0 + nb*8 + 2*q;
        float b0 = bp[col], b1 = bp[col+1];
        float2 v0 = make_float2(acc[nb][0] + b0, acc[nb][1] + b1);
        float2 v1 = make_float2(acc[nb][2] + b0, acc[nb][3] + b1);
        *reinterpret_cast<float2*>(&out[(size_t)(m0 + lr    )*D_ + col]) = v0;
        *reinterpret_cast<float2*>(&out[(size_t)(m0 + lr + 8)*D_ + col]) = v1;
    }
}

// -----------------------------------------------------------------------------
extern "C" void kernel_launch(void* const* d_in, const int* in_sizes, int n_in,
                              void* d_out, int out_size)
{
    const float* x  = (const float*)d_in[0];
    const float* Wq = (const float*)d_in[1];
    const float* bq = (const float*)d_in[2];
    const float* Wk = (const float*)d_in[3];
    const float* bk = (const float*)d_in[4];
    const float* Wv = (const float*)d_in[5];
    const float* bv = (const float*)d_in[6];
    const float* Wp = (const float*)d_in[7];
    const float* bp = (const float*)d_in[8];
    float* out = (float*)d_out;

    cudaFuncSetAttribute(qkv_kernel,  cudaFuncAttributeMaxDynamicSharedMemorySize, QKV_SMEM);
    cudaFuncSetAttribute(proj_kernel, cudaFuncAttributeMaxDynamicSharedMemorySize, QKV_SMEM);
    cudaFuncSetAttribute(attn_kernel, cudaFuncAttributeMaxDynamicSharedMemorySize, ATTN_DSMEM);

    prep_x<<<(B_*S_*D_/4 + 255)/256, 256>>>(x);
    prep_w<<<(3*H_*D_*HD_ + 255)/256, 256>>>(Wq, Wk, Wv, Wp);

    qkv_kernel<<<dim3(3*H_, S_/128, B_), 256, QKV_SMEM>>>(bq, bk, bv);
    attn_kernel<<<dim3(S_/128, BH_), 256, ATTN_DSMEM>>>();
    proj_kernel<<<dim3(D_/64, (B_*S_)/128), 256, QKV_SMEM>>>(bp, out);
}